// round 1
// baseline (speedup 1.0000x reference)
#include <cuda_runtime.h>
#include <cuda_bf16.h>
#include <math.h>

// Problem constants (fixed for this problem instance)
#define B_   2
#define S_   2048
#define H_   2048
#define NH_  16
#define NKV_ 4
#define HD_  128
#define T_   (B_ * S_)            // 4096 tokens
#define SCALE_ 0.08838834764831845f   // 128^-0.5

// ---------------------------------------------------------------------------
// Device scratch (allocation-free rule: __device__ globals)
// ---------------------------------------------------------------------------
__device__ float g_Q[T_ * NH_ * HD_];      // [4096, 2048]
__device__ float g_K[T_ * NKV_ * HD_];     // [4096, 512]
__device__ float g_V[T_ * NKV_ * HD_];     // [4096, 512]
__device__ float g_ATTN[T_ * NH_ * HD_];   // [4096, 2048]

// ---------------------------------------------------------------------------
// SGEMM: C[M,N] = A[M,K] @ B[K,N] (+ bias[N]) ; row-major, fp32.
// Classic 128x128x8 tile, 256 threads, 8x8 microtile.
// Requires: M%128==0, N%128==0, K%8==0, all pointers 16B aligned.
// ---------------------------------------------------------------------------
__global__ __launch_bounds__(256) void sgemm_kernel(
    const float* __restrict__ A, const float* __restrict__ Bm,
    const float* __restrict__ bias, float* __restrict__ C,
    int M, int N, int K)
{
    __shared__ float As[8][128];
    __shared__ float Bs[8][128];

    const int tid = threadIdx.x;
    const int bm  = blockIdx.y;
    const int bn  = blockIdx.x;

    const int ty = tid >> 4;       // 0..15
    const int tx = tid & 15;       // 0..15

    // A tile loaders: 128 rows x 8 cols = 256 float4 (2 per row)
    const int arow  = tid >> 1;          // 0..127
    const int acol  = (tid & 1) * 4;     // 0 or 4
    // B tile loaders: 8 rows x 128 cols = 256 float4
    const int brow  = tid >> 5;          // 0..7
    const int bcol4 = (tid & 31) * 4;    // 0..124 step 4

    float acc[8][8];
#pragma unroll
    for (int i = 0; i < 8; ++i)
#pragma unroll
        for (int j = 0; j < 8; ++j) acc[i][j] = 0.f;

    const float* Aptr = A + (size_t)(bm * 128) * K;
    const float* Bptr = Bm + bn * 128;

    for (int k0 = 0; k0 < K; k0 += 8) {
        float4 av = *(const float4*)(Aptr + (size_t)arow * K + k0 + acol);
        As[acol + 0][arow] = av.x;
        As[acol + 1][arow] = av.y;
        As[acol + 2][arow] = av.z;
        As[acol + 3][arow] = av.w;
        float4 bv = *(const float4*)(Bptr + (size_t)(k0 + brow) * N + bcol4);
        *(float4*)&Bs[brow][bcol4] = bv;
        __syncthreads();

#pragma unroll
        for (int kk = 0; kk < 8; ++kk) {
            float a[8], b[8];
            *(float4*)&a[0] = *(const float4*)&As[kk][ty * 8 + 0];
            *(float4*)&a[4] = *(const float4*)&As[kk][ty * 8 + 4];
            *(float4*)&b[0] = *(const float4*)&Bs[kk][tx * 8 + 0];
            *(float4*)&b[4] = *(const float4*)&Bs[kk][tx * 8 + 4];
#pragma unroll
            for (int i = 0; i < 8; ++i)
#pragma unroll
                for (int j = 0; j < 8; ++j)
                    acc[i][j] += a[i] * b[j];
        }
        __syncthreads();
    }

    float bsv[8];
    if (bias) {
        *(float4*)&bsv[0] = *(const float4*)(bias + bn * 128 + tx * 8 + 0);
        *(float4*)&bsv[4] = *(const float4*)(bias + bn * 128 + tx * 8 + 4);
    } else {
#pragma unroll
        for (int j = 0; j < 8; ++j) bsv[j] = 0.f;
    }

#pragma unroll
    for (int i = 0; i < 8; ++i) {
        int row = bm * 128 + ty * 8 + i;
        float4 o0, o1;
        o0.x = acc[i][0] + bsv[0]; o0.y = acc[i][1] + bsv[1];
        o0.z = acc[i][2] + bsv[2]; o0.w = acc[i][3] + bsv[3];
        o1.x = acc[i][4] + bsv[4]; o1.y = acc[i][5] + bsv[5];
        o1.z = acc[i][6] + bsv[6]; o1.w = acc[i][7] + bsv[7];
        *(float4*)(C + (size_t)row * N + bn * 128 + tx * 8 + 0) = o0;
        *(float4*)(C + (size_t)row * N + bn * 128 + tx * 8 + 4) = o1;
    }
}

// ---------------------------------------------------------------------------
// Neox RoPE applied in-place to x[T, nheads*128].
// One thread per (token, head, freq-index i<64).
// ---------------------------------------------------------------------------
__global__ void rope_kernel(float* __restrict__ x, const int* __restrict__ positions,
                            int Ttot, int nheads)
{
    int idx = blockIdx.x * blockDim.x + threadIdx.x;
    int total = Ttot * nheads * (HD_ / 2);
    if (idx >= total) return;
    int i = idx & 63;                // 0..63
    int h = (idx >> 6) % nheads;
    int t = idx / (64 * nheads);

    int pos = positions[t % S_];
    // inv_freq = theta^(-2i/HD)
    float inv_freq = powf(10000.0f, -((float)(2 * i)) / (float)HD_);
    float freq = (float)pos * inv_freq;
    float s, c;
    sincosf(freq, &s, &c);

    size_t base = (size_t)t * (nheads * HD_) + h * HD_;
    float x1 = x[base + i];
    float x2 = x[base + 64 + i];
    x[base + i]      = x1 * c - x2 * s;
    x[base + 64 + i] = x2 * c + x1 * s;
}

// ---------------------------------------------------------------------------
// Flash attention (fp32, causal, GQA rep=4).
// Grid: (S/64, NH, B); 256 threads as 16x16.
// SMEM: sQ[64][132] | sK[128][64] (K transposed; P[64][68] overlays) | sV[64][128]
// ---------------------------------------------------------------------------
#define FA_BM 64
#define FA_BN 64
#define QPAD 132
#define PPAD 68

__global__ __launch_bounds__(256) void flash_attn_kernel(
    const float* __restrict__ Q, const float* __restrict__ K,
    const float* __restrict__ V, float* __restrict__ O)
{
    extern __shared__ float sm[];
    float* sQ = sm;                        // 64*132
    float* sK = sm + FA_BM * QPAD;         // 128*64 (transposed), P overlays
    float* sV = sK + HD_ * FA_BN;          // 64*128
    float* sP = sK;                        // 64*68 overlay
    __shared__ float s_m[FA_BM];
    __shared__ float s_l[FA_BM];

    const int qt = blockIdx.x;
    const int h  = blockIdx.y;
    const int b  = blockIdx.z;
    const int kvh = h >> 2;                // GQA: repeat -> kv head = h/4

    const int tid = threadIdx.x;
    const int ty = tid >> 4;               // 0..15
    const int tx = tid & 15;               // 0..15
    const int q0 = qt * FA_BM;

    const float* Qbase = Q + (size_t)b * S_ * (NH_ * HD_)  + h * HD_;
    const float* Kbase = K + (size_t)b * S_ * (NKV_ * HD_) + kvh * HD_;
    const float* Vbase = V + (size_t)b * S_ * (NKV_ * HD_) + kvh * HD_;

    // Load Q tile: 64 rows x 128 dims = 2048 float4
#pragma unroll
    for (int i = 0; i < 8; ++i) {
        int lin = i * 256 + tid;
        int r   = lin >> 5;
        int d4  = (lin & 31) * 4;
        float4 v = *(const float4*)(Qbase + (size_t)(q0 + r) * (NH_ * HD_) + d4);
        *(float4*)(sQ + r * QPAD + d4) = v;
    }
    if (tid < FA_BM) { s_m[tid] = -1e30f; s_l[tid] = 0.f; }

    float acc[4][8];
#pragma unroll
    for (int r = 0; r < 4; ++r)
#pragma unroll
        for (int c = 0; c < 8; ++c) acc[r][c] = 0.f;

    __syncthreads();   // Q + stats ready

    const int row0 = ty * 4;

    for (int j = 0; j <= qt; ++j) {
        const int k0 = j * FA_BN;

        // Load K (transposed into sK[d][tok]) and V (natural) : 2048 float4 each
#pragma unroll
        for (int i = 0; i < 8; ++i) {
            int lin = i * 256 + tid;
            int tok = lin >> 5;
            int d4  = (lin & 31) * 4;
            float4 kv = *(const float4*)(Kbase + (size_t)(k0 + tok) * (NKV_ * HD_) + d4);
            sK[(d4 + 0) * FA_BN + tok] = kv.x;
            sK[(d4 + 1) * FA_BN + tok] = kv.y;
            sK[(d4 + 2) * FA_BN + tok] = kv.z;
            sK[(d4 + 3) * FA_BN + tok] = kv.w;
            float4 vv = *(const float4*)(Vbase + (size_t)(k0 + tok) * (NKV_ * HD_) + d4);
            *(float4*)(sV + tok * HD_ + d4) = vv;
        }
        __syncthreads();

        // Scores S = Q @ K^T  (64x64, 4x4 per thread)
        float sacc[4][4];
#pragma unroll
        for (int r = 0; r < 4; ++r)
#pragma unroll
            for (int c = 0; c < 4; ++c) sacc[r][c] = 0.f;

#pragma unroll 4
        for (int k4 = 0; k4 < 32; ++k4) {
            float qv[4][4];
#pragma unroll
            for (int r = 0; r < 4; ++r)
                *(float4*)qv[r] = *(const float4*)(sQ + (row0 + r) * QPAD + k4 * 4);
#pragma unroll
            for (int kk = 0; kk < 4; ++kk) {
                float4 kv = *(const float4*)(sK + (k4 * 4 + kk) * FA_BN + tx * 4);
#pragma unroll
                for (int r = 0; r < 4; ++r) {
                    float q = qv[r][kk];
                    sacc[r][0] += q * kv.x;
                    sacc[r][1] += q * kv.y;
                    sacc[r][2] += q * kv.z;
                    sacc[r][3] += q * kv.w;
                }
            }
        }

        // Scale + causal mask (only diagonal tile can mask)
        const bool diag = (j == qt);
#pragma unroll
        for (int r = 0; r < 4; ++r) {
            int qi = q0 + row0 + r;
#pragma unroll
            for (int c = 0; c < 4; ++c) {
                float s = sacc[r][c] * SCALE_;
                if (diag && (k0 + tx * 4 + c) > qi) s = -1e30f;
                sacc[r][c] = s;
            }
        }

        // Online softmax update (per row group of 16 lanes)
        float p[4][4];
        float m_new[4], alpha[4], rsum[4];
#pragma unroll
        for (int r = 0; r < 4; ++r) {
            float mx = fmaxf(fmaxf(sacc[r][0], sacc[r][1]), fmaxf(sacc[r][2], sacc[r][3]));
#pragma unroll
            for (int off = 8; off >= 1; off >>= 1)
                mx = fmaxf(mx, __shfl_xor_sync(0xffffffffu, mx, off, 16));
            float m_old = s_m[row0 + r];
            m_new[r] = fmaxf(m_old, mx);
            alpha[r] = __expf(m_old - m_new[r]);
            float rs = 0.f;
#pragma unroll
            for (int c = 0; c < 4; ++c) {
                p[r][c] = __expf(sacc[r][c] - m_new[r]);
                rs += p[r][c];
            }
#pragma unroll
            for (int off = 8; off >= 1; off >>= 1)
                rs += __shfl_xor_sync(0xffffffffu, rs, off, 16);
            rsum[r] = rs;
        }
        // rescale accumulator
#pragma unroll
        for (int r = 0; r < 4; ++r)
#pragma unroll
            for (int c = 0; c < 8; ++c) acc[r][c] *= alpha[r];

        __syncwarp();
        if (tx == 0) {
#pragma unroll
            for (int r = 0; r < 4; ++r) {
                s_m[row0 + r] = m_new[r];
                s_l[row0 + r] = s_l[row0 + r] * alpha[r] + rsum[r];
            }
        }

        __syncthreads();   // all done reading sK -> safe to overlay P
#pragma unroll
        for (int r = 0; r < 4; ++r)
            *(float4*)(sP + (row0 + r) * PPAD + tx * 4) = *(float4*)p[r];
        __syncthreads();

        // O += P @ V  (rows: ty*4.., cols: tx*8..)
#pragma unroll 4
        for (int kk = 0; kk < FA_BN; ++kk) {
            float pv[4];
#pragma unroll
            for (int r = 0; r < 4; ++r) pv[r] = sP[(row0 + r) * PPAD + kk];
            float4 v0 = *(const float4*)(sV + kk * HD_ + tx * 8 + 0);
            float4 v1 = *(const float4*)(sV + kk * HD_ + tx * 8 + 4);
#pragma unroll
            for (int r = 0; r < 4; ++r) {
                acc[r][0] += pv[r] * v0.x; acc[r][1] += pv[r] * v0.y;
                acc[r][2] += pv[r] * v0.z; acc[r][3] += pv[r] * v0.w;
                acc[r][4] += pv[r] * v1.x; acc[r][5] += pv[r] * v1.y;
                acc[r][6] += pv[r] * v1.z; acc[r][7] += pv[r] * v1.w;
            }
        }
        __syncthreads();   // protect sK/sV/sP for next iteration
    }

    // Epilogue: divide by l, write to g_ATTN[t][h*128 + d]
#pragma unroll
    for (int r = 0; r < 4; ++r) {
        float inv = 1.0f / s_l[row0 + r];
        size_t t = (size_t)b * S_ + q0 + row0 + r;
        float4 o0, o1;
        o0.x = acc[r][0] * inv; o0.y = acc[r][1] * inv;
        o0.z = acc[r][2] * inv; o0.w = acc[r][3] * inv;
        o1.x = acc[r][4] * inv; o1.y = acc[r][5] * inv;
        o1.z = acc[r][6] * inv; o1.w = acc[r][7] * inv;
        float* op = O + t * (NH_ * HD_) + h * HD_ + tx * 8;
        *(float4*)(op + 0) = o0;
        *(float4*)(op + 4) = o1;
    }
}

// ---------------------------------------------------------------------------
// Launch
// ---------------------------------------------------------------------------
extern "C" void kernel_launch(void* const* d_in, const int* in_sizes, int n_in,
                              void* d_out, int out_size)
{
    const float* hidden = (const float*)d_in[0];
    const int*   positions = (const int*)d_in[1];
    const float* Wq = (const float*)d_in[2];
    const float* bq = (const float*)d_in[3];
    const float* Wk = (const float*)d_in[4];
    const float* bk = (const float*)d_in[5];
    const float* Wv = (const float*)d_in[6];
    const float* bv = (const float*)d_in[7];
    const float* Wo = (const float*)d_in[8];
    float* out = (float*)d_out;

    void *pQ, *pK, *pV, *pA;
    cudaGetSymbolAddress(&pQ, g_Q);
    cudaGetSymbolAddress(&pK, g_K);
    cudaGetSymbolAddress(&pV, g_V);
    cudaGetSymbolAddress(&pA, g_ATTN);
    float* Qs = (float*)pQ;
    float* Ks = (float*)pK;
    float* Vs = (float*)pV;
    float* As = (float*)pA;

    // QKV projections
    sgemm_kernel<<<dim3((NH_ * HD_) / 128, T_ / 128), 256>>>(hidden, Wq, bq, Qs, T_, NH_ * HD_, H_);
    sgemm_kernel<<<dim3((NKV_ * HD_) / 128, T_ / 128), 256>>>(hidden, Wk, bk, Ks, T_, NKV_ * HD_, H_);
    sgemm_kernel<<<dim3((NKV_ * HD_) / 128, T_ / 128), 256>>>(hidden, Wv, bv, Vs, T_, NKV_ * HD_, H_);

    // RoPE on Q and K
    {
        int totq = T_ * NH_ * 64;
        rope_kernel<<<(totq + 255) / 256, 256>>>(Qs, positions, T_, NH_);
        int totk = T_ * NKV_ * 64;
        rope_kernel<<<(totk + 255) / 256, 256>>>(Ks, positions, T_, NKV_);
    }

    // Flash attention
    size_t fa_smem = (size_t)(FA_BM * QPAD + HD_ * FA_BN + FA_BM * HD_) * sizeof(float);
    cudaFuncSetAttribute(flash_attn_kernel, cudaFuncAttributeMaxDynamicSharedMemorySize, (int)fa_smem);
    flash_attn_kernel<<<dim3(S_ / FA_BM, NH_, B_), 256, fa_smem>>>(Qs, Ks, Vs, As);

    // Output projection
    sgemm_kernel<<<dim3(H_ / 128, T_ / 128), 256>>>(As, Wo, nullptr, out, T_, H_, NH_ * HD_);
}

// round 3
// speedup vs baseline: 1.1360x; 1.1360x over previous
#include <cuda_runtime.h>
#include <cuda_bf16.h>
#include <math.h>
#include <stdint.h>

// Problem constants (fixed for this problem instance)
#define B_   2
#define S_   2048
#define H_   2048
#define NH_  16
#define NKV_ 4
#define HD_  128
#define T_   (B_ * S_)            // 4096 tokens
#define SCALE_ 0.08838834764831845f   // 128^-0.5

// ---------------------------------------------------------------------------
// Device scratch (allocation-free rule: __device__ globals)
// ---------------------------------------------------------------------------
__device__ float g_Q[T_ * NH_ * HD_];      // [4096, 2048]
__device__ float g_K[T_ * NKV_ * HD_];     // [4096, 512]
__device__ float g_V[T_ * NKV_ * HD_];     // [4096, 512]
__device__ float g_ATTN[T_ * NH_ * HD_];   // [4096, 2048]

// ---------------------------------------------------------------------------
// TF32 helpers
// ---------------------------------------------------------------------------
__device__ __forceinline__ uint32_t f2tf32_bits(float x) {
    uint32_t y;
    asm("cvt.rna.tf32.f32 %0, %1;" : "=r"(y) : "f"(x));
    return y;
}
__device__ __forceinline__ void split_tf32(float x, float& h, float& l) {
    uint32_t hb = f2tf32_bits(x);
    h = __uint_as_float(hb);
    l = __uint_as_float(f2tf32_bits(x - h));
}
__device__ __forceinline__ void mma_tf32(float* d, const uint32_t* a, const uint32_t* b) {
    asm volatile(
        "mma.sync.aligned.m16n8k8.row.col.f32.tf32.tf32.f32 "
        "{%0,%1,%2,%3}, {%4,%5,%6,%7}, {%8,%9}, {%0,%1,%2,%3};"
        : "+f"(d[0]), "+f"(d[1]), "+f"(d[2]), "+f"(d[3])
        : "r"(a[0]), "r"(a[1]), "r"(a[2]), "r"(a[3]), "r"(b[0]), "r"(b[1]));
}

// ---------------------------------------------------------------------------
// TF32 tensor-core GEMM with 3xTF32 correction (fp32-accurate).
// C[M,N] = A[M,K] @ B[K,N] (+ bias[N]); row-major.
// Tile 128x128x16, 256 threads (8 warps as 2x4), warp tile 64x32.
// Requires M%128==0, N%128==0, K%16==0.
// ---------------------------------------------------------------------------
#define GM_APAD 20
#define GM_BPAD 136

__global__ __launch_bounds__(256) void tf32_gemm_kernel(
    const float* __restrict__ A, const float* __restrict__ Bm,
    const float* __restrict__ bias, float* __restrict__ C,
    int M, int N, int K)
{
    __shared__ float Ah[128][GM_APAD];
    __shared__ float Al[128][GM_APAD];
    __shared__ float Bh[16][GM_BPAD];
    __shared__ float Bl[16][GM_BPAD];

    const int tid  = threadIdx.x;
    const int warp = tid >> 5;
    const int lane = tid & 31;
    const int g    = lane >> 2;   // 0..7
    const int tg   = lane & 3;    // 0..3
    const int wm   = warp >> 2;   // 0..1
    const int wn   = warp & 3;    // 0..3

    const int bm = blockIdx.y;
    const int bn = blockIdx.x;

    const float* Ab = A + (size_t)(bm * 128) * K;
    const float* Bb = Bm + bn * 128;

    float acc[4][4][4];
#pragma unroll
    for (int mi = 0; mi < 4; ++mi)
#pragma unroll
        for (int ni = 0; ni < 4; ++ni)
#pragma unroll
            for (int r = 0; r < 4; ++r) acc[mi][ni][r] = 0.f;

    float4 aReg[2], bReg[2];

    // global tile load into registers
    auto load_tile = [&](int k0) {
#pragma unroll
        for (int i = 0; i < 2; ++i) {
            int lin = i * 256 + tid;
            aReg[i] = *(const float4*)(Ab + (size_t)(lin >> 2) * K + k0 + (lin & 3) * 4);
            bReg[i] = *(const float4*)(Bb + (size_t)(k0 + (lin >> 5)) * N + (lin & 31) * 4);
        }
    };
    // split into tf32 hi/lo and store to smem
    auto store_tile = [&]() {
#pragma unroll
        for (int i = 0; i < 2; ++i) {
            int lin = i * 256 + tid;
            {
                int ar = lin >> 2, ac = (lin & 3) * 4;
                float4 v = aReg[i];
                float4 h, l;
                split_tf32(v.x, h.x, l.x); split_tf32(v.y, h.y, l.y);
                split_tf32(v.z, h.z, l.z); split_tf32(v.w, h.w, l.w);
                *(float4*)&Ah[ar][ac] = h;
                *(float4*)&Al[ar][ac] = l;
            }
            {
                int br = lin >> 5, bc = (lin & 31) * 4;
                float4 v = bReg[i];
                float4 h, l;
                split_tf32(v.x, h.x, l.x); split_tf32(v.y, h.y, l.y);
                split_tf32(v.z, h.z, l.z); split_tf32(v.w, h.w, l.w);
                *(float4*)&Bh[br][bc] = h;
                *(float4*)&Bl[br][bc] = l;
            }
        }
    };

    const int ntiles = K / 16;

    load_tile(0);
    store_tile();
    __syncthreads();

    for (int t = 0; t < ntiles; ++t) {
        if (t + 1 < ntiles) load_tile((t + 1) * 16);

#pragma unroll
        for (int ks = 0; ks < 2; ++ks) {
            uint32_t ah[4][4], al[4][4];
            uint32_t bh[4][2], bl[4][2];
#pragma unroll
            for (int mi = 0; mi < 4; ++mi) {
                int r0 = wm * 64 + mi * 16 + g;
                int c0 = ks * 8 + tg;
                ah[mi][0] = __float_as_uint(Ah[r0][c0]);
                ah[mi][1] = __float_as_uint(Ah[r0 + 8][c0]);
                ah[mi][2] = __float_as_uint(Ah[r0][c0 + 4]);
                ah[mi][3] = __float_as_uint(Ah[r0 + 8][c0 + 4]);
                al[mi][0] = __float_as_uint(Al[r0][c0]);
                al[mi][1] = __float_as_uint(Al[r0 + 8][c0]);
                al[mi][2] = __float_as_uint(Al[r0][c0 + 4]);
                al[mi][3] = __float_as_uint(Al[r0 + 8][c0 + 4]);
            }
#pragma unroll
            for (int ni = 0; ni < 4; ++ni) {
                int c0 = wn * 32 + ni * 8 + g;
                int r0 = ks * 8 + tg;
                bh[ni][0] = __float_as_uint(Bh[r0][c0]);
                bh[ni][1] = __float_as_uint(Bh[r0 + 4][c0]);
                bl[ni][0] = __float_as_uint(Bl[r0][c0]);
                bl[ni][1] = __float_as_uint(Bl[r0 + 4][c0]);
            }
#pragma unroll
            for (int mi = 0; mi < 4; ++mi)
#pragma unroll
                for (int ni = 0; ni < 4; ++ni) {
                    mma_tf32(acc[mi][ni], ah[mi], bh[ni]);
                    mma_tf32(acc[mi][ni], al[mi], bh[ni]);
                    mma_tf32(acc[mi][ni], ah[mi], bl[ni]);
                }
        }
        __syncthreads();
        if (t + 1 < ntiles) {
            store_tile();
            __syncthreads();
        }
    }

    // Epilogue: add bias, write out
#pragma unroll
    for (int mi = 0; mi < 4; ++mi) {
        int r0 = bm * 128 + wm * 64 + mi * 16 + g;
#pragma unroll
        for (int ni = 0; ni < 4; ++ni) {
            int c = bn * 128 + wn * 32 + ni * 8 + 2 * tg;
            float b0 = 0.f, b1 = 0.f;
            if (bias) { b0 = bias[c]; b1 = bias[c + 1]; }
            float2 o0, o1;
            o0.x = acc[mi][ni][0] + b0; o0.y = acc[mi][ni][1] + b1;
            o1.x = acc[mi][ni][2] + b0; o1.y = acc[mi][ni][3] + b1;
            *(float2*)(C + (size_t)r0 * N + c)       = o0;
            *(float2*)(C + (size_t)(r0 + 8) * N + c) = o1;
        }
    }
}

// ---------------------------------------------------------------------------
// Neox RoPE applied in-place to x[T, nheads*128].
// ---------------------------------------------------------------------------
__global__ void rope_kernel(float* __restrict__ x, const int* __restrict__ positions,
                            int Ttot, int nheads)
{
    int idx = blockIdx.x * blockDim.x + threadIdx.x;
    int total = Ttot * nheads * (HD_ / 2);
    if (idx >= total) return;
    int i = idx & 63;
    int h = (idx >> 6) % nheads;
    int t = idx / (64 * nheads);

    int pos = positions[t % S_];
    float inv_freq = powf(10000.0f, -((float)(2 * i)) / (float)HD_);
    float freq = (float)pos * inv_freq;
    float s, c;
    sincosf(freq, &s, &c);

    size_t base = (size_t)t * (nheads * HD_) + h * HD_;
    float x1 = x[base + i];
    float x2 = x[base + 64 + i];
    x[base + i]      = x1 * c - x2 * s;
    x[base + 64 + i] = x2 * c + x1 * s;
}

// ---------------------------------------------------------------------------
// Flash attention (fp32, causal, GQA rep=4).
// ---------------------------------------------------------------------------
#define FA_BM 64
#define FA_BN 64
#define QPAD 132
#define PPAD 68

__global__ __launch_bounds__(256) void flash_attn_kernel(
    const float* __restrict__ Q, const float* __restrict__ K,
    const float* __restrict__ V, float* __restrict__ O)
{
    extern __shared__ float sm[];
    float* sQ = sm;                        // 64*132
    float* sK = sm + FA_BM * QPAD;         // 128*64 (transposed), P overlays
    float* sV = sK + HD_ * FA_BN;          // 64*128
    float* sP = sK;                        // 64*68 overlay
    __shared__ float s_m[FA_BM];
    __shared__ float s_l[FA_BM];

    const int qt = blockIdx.x;
    const int h  = blockIdx.y;
    const int b  = blockIdx.z;
    const int kvh = h >> 2;

    const int tid = threadIdx.x;
    const int ty = tid >> 4;
    const int tx = tid & 15;
    const int q0 = qt * FA_BM;

    const float* Qbase = Q + (size_t)b * S_ * (NH_ * HD_)  + h * HD_;
    const float* Kbase = K + (size_t)b * S_ * (NKV_ * HD_) + kvh * HD_;
    const float* Vbase = V + (size_t)b * S_ * (NKV_ * HD_) + kvh * HD_;

#pragma unroll
    for (int i = 0; i < 8; ++i) {
        int lin = i * 256 + tid;
        int r   = lin >> 5;
        int d4  = (lin & 31) * 4;
        float4 v = *(const float4*)(Qbase + (size_t)(q0 + r) * (NH_ * HD_) + d4);
        *(float4*)(sQ + r * QPAD + d4) = v;
    }
    if (tid < FA_BM) { s_m[tid] = -1e30f; s_l[tid] = 0.f; }

    float acc[4][8];
#pragma unroll
    for (int r = 0; r < 4; ++r)
#pragma unroll
        for (int c = 0; c < 8; ++c) acc[r][c] = 0.f;

    __syncthreads();

    const int row0 = ty * 4;

    for (int j = 0; j <= qt; ++j) {
        const int k0 = j * FA_BN;

#pragma unroll
        for (int i = 0; i < 8; ++i) {
            int lin = i * 256 + tid;
            int tok = lin >> 5;
            int d4  = (lin & 31) * 4;
            float4 kv = *(const float4*)(Kbase + (size_t)(k0 + tok) * (NKV_ * HD_) + d4);
            sK[(d4 + 0) * FA_BN + tok] = kv.x;
            sK[(d4 + 1) * FA_BN + tok] = kv.y;
            sK[(d4 + 2) * FA_BN + tok] = kv.z;
            sK[(d4 + 3) * FA_BN + tok] = kv.w;
            float4 vv = *(const float4*)(Vbase + (size_t)(k0 + tok) * (NKV_ * HD_) + d4);
            *(float4*)(sV + tok * HD_ + d4) = vv;
        }
        __syncthreads();

        float sacc[4][4];
#pragma unroll
        for (int r = 0; r < 4; ++r)
#pragma unroll
            for (int c = 0; c < 4; ++c) sacc[r][c] = 0.f;

#pragma unroll 4
        for (int k4 = 0; k4 < 32; ++k4) {
            float qv[4][4];
#pragma unroll
            for (int r = 0; r < 4; ++r)
                *(float4*)qv[r] = *(const float4*)(sQ + (row0 + r) * QPAD + k4 * 4);
#pragma unroll
            for (int kk = 0; kk < 4; ++kk) {
                float4 kv = *(const float4*)(sK + (k4 * 4 + kk) * FA_BN + tx * 4);
#pragma unroll
                for (int r = 0; r < 4; ++r) {
                    float q = qv[r][kk];
                    sacc[r][0] += q * kv.x;
                    sacc[r][1] += q * kv.y;
                    sacc[r][2] += q * kv.z;
                    sacc[r][3] += q * kv.w;
                }
            }
        }

        const bool diag = (j == qt);
#pragma unroll
        for (int r = 0; r < 4; ++r) {
            int qi = q0 + row0 + r;
#pragma unroll
            for (int c = 0; c < 4; ++c) {
                float s = sacc[r][c] * SCALE_;
                if (diag && (k0 + tx * 4 + c) > qi) s = -1e30f;
                sacc[r][c] = s;
            }
        }

        float p[4][4];
        float m_new[4], alpha[4], rsum[4];
#pragma unroll
        for (int r = 0; r < 4; ++r) {
            float mx = fmaxf(fmaxf(sacc[r][0], sacc[r][1]), fmaxf(sacc[r][2], sacc[r][3]));
#pragma unroll
            for (int off = 8; off >= 1; off >>= 1)
                mx = fmaxf(mx, __shfl_xor_sync(0xffffffffu, mx, off, 16));
            float m_old = s_m[row0 + r];
            m_new[r] = fmaxf(m_old, mx);
            alpha[r] = __expf(m_old - m_new[r]);
            float rs = 0.f;
#pragma unroll
            for (int c = 0; c < 4; ++c) {
                p[r][c] = __expf(sacc[r][c] - m_new[r]);
                rs += p[r][c];
            }
#pragma unroll
            for (int off = 8; off >= 1; off >>= 1)
                rs += __shfl_xor_sync(0xffffffffu, rs, off, 16);
            rsum[r] = rs;
        }
#pragma unroll
        for (int r = 0; r < 4; ++r)
#pragma unroll
            for (int c = 0; c < 8; ++c) acc[r][c] *= alpha[r];

        __syncwarp();
        if (tx == 0) {
#pragma unroll
            for (int r = 0; r < 4; ++r) {
                s_m[row0 + r] = m_new[r];
                s_l[row0 + r] = s_l[row0 + r] * alpha[r] + rsum[r];
            }
        }

        __syncthreads();
#pragma unroll
        for (int r = 0; r < 4; ++r)
            *(float4*)(sP + (row0 + r) * PPAD + tx * 4) = *(float4*)p[r];
        __syncthreads();

#pragma unroll 4
        for (int kk = 0; kk < FA_BN; ++kk) {
            float pv[4];
#pragma unroll
            for (int r = 0; r < 4; ++r) pv[r] = sP[(row0 + r) * PPAD + kk];
            float4 v0 = *(const float4*)(sV + kk * HD_ + tx * 8 + 0);
            float4 v1 = *(const float4*)(sV + kk * HD_ + tx * 8 + 4);
#pragma unroll
            for (int r = 0; r < 4; ++r) {
                acc[r][0] += pv[r] * v0.x; acc[r][1] += pv[r] * v0.y;
                acc[r][2] += pv[r] * v0.z; acc[r][3] += pv[r] * v0.w;
                acc[r][4] += pv[r] * v1.x; acc[r][5] += pv[r] * v1.y;
                acc[r][6] += pv[r] * v1.z; acc[r][7] += pv[r] * v1.w;
            }
        }
        __syncthreads();
    }

#pragma unroll
    for (int r = 0; r < 4; ++r) {
        float inv = 1.0f / s_l[row0 + r];
        size_t t = (size_t)b * S_ + q0 + row0 + r;
        float4 o0, o1;
        o0.x = acc[r][0] * inv; o0.y = acc[r][1] * inv;
        o0.z = acc[r][2] * inv; o0.w = acc[r][3] * inv;
        o1.x = acc[r][4] * inv; o1.y = acc[r][5] * inv;
        o1.z = acc[r][6] * inv; o1.w = acc[r][7] * inv;
        float* op = O + t * (NH_ * HD_) + h * HD_ + tx * 8;
        *(float4*)(op + 0) = o0;
        *(float4*)(op + 4) = o1;
    }
}

// ---------------------------------------------------------------------------
// Launch
// ---------------------------------------------------------------------------
extern "C" void kernel_launch(void* const* d_in, const int* in_sizes, int n_in,
                              void* d_out, int out_size)
{
    const float* hidden = (const float*)d_in[0];
    const int*   positions = (const int*)d_in[1];
    const float* Wq = (const float*)d_in[2];
    const float* bq = (const float*)d_in[3];
    const float* Wk = (const float*)d_in[4];
    const float* bk = (const float*)d_in[5];
    const float* Wv = (const float*)d_in[6];
    const float* bv = (const float*)d_in[7];
    const float* Wo = (const float*)d_in[8];
    float* out = (float*)d_out;

    void *pQ, *pK, *pV, *pA;
    cudaGetSymbolAddress(&pQ, g_Q);
    cudaGetSymbolAddress(&pK, g_K);
    cudaGetSymbolAddress(&pV, g_V);
    cudaGetSymbolAddress(&pA, g_ATTN);
    float* Qs = (float*)pQ;
    float* Ks = (float*)pK;
    float* Vs = (float*)pV;
    float* As = (float*)pA;

    // QKV projections (tensor cores, 3xTF32)
    tf32_gemm_kernel<<<dim3((NH_ * HD_) / 128, T_ / 128), 256>>>(hidden, Wq, bq, Qs, T_, NH_ * HD_, H_);
    tf32_gemm_kernel<<<dim3((NKV_ * HD_) / 128, T_ / 128), 256>>>(hidden, Wk, bk, Ks, T_, NKV_ * HD_, H_);
    tf32_gemm_kernel<<<dim3((NKV_ * HD_) / 128, T_ / 128), 256>>>(hidden, Wv, bv, Vs, T_, NKV_ * HD_, H_);

    // RoPE on Q and K
    {
        int totq = T_ * NH_ * 64;
        rope_kernel<<<(totq + 255) / 256, 256>>>(Qs, positions, T_, NH_);
        int totk = T_ * NKV_ * 64;
        rope_kernel<<<(totk + 255) / 256, 256>>>(Ks, positions, T_, NKV_);
    }

    // Flash attention
    size_t fa_smem = (size_t)(FA_BM * QPAD + HD_ * FA_BN + FA_BM * HD_) * sizeof(float);
    cudaFuncSetAttribute(flash_attn_kernel, cudaFuncAttributeMaxDynamicSharedMemorySize, (int)fa_smem);
    flash_attn_kernel<<<dim3(S_ / FA_BM, NH_, B_), 256, fa_smem>>>(Qs, Ks, Vs, As);

    // Output projection (tensor cores, 3xTF32)
    tf32_gemm_kernel<<<dim3(H_ / 128, T_ / 128), 256>>>(As, Wo, nullptr, out, T_, H_, NH_ * HD_);
}

// round 6
// speedup vs baseline: 1.3109x; 1.1539x over previous
#include <cuda_runtime.h>
#include <cuda_bf16.h>
#include <math.h>
#include <stdint.h>

// Problem constants (fixed for this problem instance)
#define B_   2
#define S_   2048
#define H_   2048
#define NH_  16
#define NKV_ 4
#define HD_  128
#define T_   (B_ * S_)            // 4096 tokens
#define SCALE_ 0.08838834764831845f   // 128^-0.5

// ---------------------------------------------------------------------------
// Device scratch (allocation-free rule: __device__ globals)
// ---------------------------------------------------------------------------
__device__ float g_Q[T_ * NH_ * HD_];      // [4096, 2048]
__device__ float g_K[T_ * NKV_ * HD_];     // [4096, 512]
__device__ float g_V[T_ * NKV_ * HD_];     // [4096, 512]
__device__ float g_ATTN[T_ * NH_ * HD_];   // [4096, 2048]

// ---------------------------------------------------------------------------
// TF32 helpers
// ---------------------------------------------------------------------------
__device__ __forceinline__ uint32_t f2tf32_bits(float x) {
    uint32_t y;
    asm("cvt.rna.tf32.f32 %0, %1;" : "=r"(y) : "f"(x));
    return y;
}
__device__ __forceinline__ float f2tf32(float x) {
    return __uint_as_float(f2tf32_bits(x));
}
__device__ __forceinline__ void split_tf32(float x, float& h, float& l) {
    h = f2tf32(x);
    l = __uint_as_float(f2tf32_bits(x - h));
}
__device__ __forceinline__ void mma_tf32(float* d, const uint32_t* a, const uint32_t* b) {
    asm volatile(
        "mma.sync.aligned.m16n8k8.row.col.f32.tf32.tf32.f32 "
        "{%0,%1,%2,%3}, {%4,%5,%6,%7}, {%8,%9}, {%0,%1,%2,%3};"
        : "+f"(d[0]), "+f"(d[1]), "+f"(d[2]), "+f"(d[3])
        : "r"(a[0]), "r"(a[1]), "r"(a[2]), "r"(a[3]), "r"(b[0]), "r"(b[1]));
}

// ---------------------------------------------------------------------------
// TF32 tensor-core GEMM with 3xTF32 correction (fp32-accurate).
// (unchanged from the R3 passing version)
// ---------------------------------------------------------------------------
#define GM_APAD 20
#define GM_BPAD 136

__global__ __launch_bounds__(256) void tf32_gemm_kernel(
    const float* __restrict__ A, const float* __restrict__ Bm,
    const float* __restrict__ bias, float* __restrict__ C,
    int M, int N, int K)
{
    __shared__ float Ah[128][GM_APAD];
    __shared__ float Al[128][GM_APAD];
    __shared__ float Bh[16][GM_BPAD];
    __shared__ float Bl[16][GM_BPAD];

    const int tid  = threadIdx.x;
    const int warp = tid >> 5;
    const int lane = tid & 31;
    const int g    = lane >> 2;
    const int tg   = lane & 3;
    const int wm   = warp >> 2;
    const int wn   = warp & 3;

    const int bm = blockIdx.y;
    const int bn = blockIdx.x;

    const float* Ab = A + (size_t)(bm * 128) * K;
    const float* Bb = Bm + bn * 128;

    float acc[4][4][4];
#pragma unroll
    for (int mi = 0; mi < 4; ++mi)
#pragma unroll
        for (int ni = 0; ni < 4; ++ni)
#pragma unroll
            for (int r = 0; r < 4; ++r) acc[mi][ni][r] = 0.f;

    float4 aReg[2], bReg[2];

    auto load_tile = [&](int k0) {
#pragma unroll
        for (int i = 0; i < 2; ++i) {
            int lin = i * 256 + tid;
            aReg[i] = *(const float4*)(Ab + (size_t)(lin >> 2) * K + k0 + (lin & 3) * 4);
            bReg[i] = *(const float4*)(Bb + (size_t)(k0 + (lin >> 5)) * N + (lin & 31) * 4);
        }
    };
    auto store_tile = [&]() {
#pragma unroll
        for (int i = 0; i < 2; ++i) {
            int lin = i * 256 + tid;
            {
                int ar = lin >> 2, ac = (lin & 3) * 4;
                float4 v = aReg[i];
                float4 h, l;
                split_tf32(v.x, h.x, l.x); split_tf32(v.y, h.y, l.y);
                split_tf32(v.z, h.z, l.z); split_tf32(v.w, h.w, l.w);
                *(float4*)&Ah[ar][ac] = h;
                *(float4*)&Al[ar][ac] = l;
            }
            {
                int br = lin >> 5, bc = (lin & 31) * 4;
                float4 v = bReg[i];
                float4 h, l;
                split_tf32(v.x, h.x, l.x); split_tf32(v.y, h.y, l.y);
                split_tf32(v.z, h.z, l.z); split_tf32(v.w, h.w, l.w);
                *(float4*)&Bh[br][bc] = h;
                *(float4*)&Bl[br][bc] = l;
            }
        }
    };

    const int ntiles = K / 16;

    load_tile(0);
    store_tile();
    __syncthreads();

    for (int t = 0; t < ntiles; ++t) {
        if (t + 1 < ntiles) load_tile((t + 1) * 16);

#pragma unroll
        for (int ks = 0; ks < 2; ++ks) {
            uint32_t ah[4][4], al[4][4];
            uint32_t bh[4][2], bl[4][2];
#pragma unroll
            for (int mi = 0; mi < 4; ++mi) {
                int r0 = wm * 64 + mi * 16 + g;
                int c0 = ks * 8 + tg;
                ah[mi][0] = __float_as_uint(Ah[r0][c0]);
                ah[mi][1] = __float_as_uint(Ah[r0 + 8][c0]);
                ah[mi][2] = __float_as_uint(Ah[r0][c0 + 4]);
                ah[mi][3] = __float_as_uint(Ah[r0 + 8][c0 + 4]);
                al[mi][0] = __float_as_uint(Al[r0][c0]);
                al[mi][1] = __float_as_uint(Al[r0 + 8][c0]);
                al[mi][2] = __float_as_uint(Al[r0][c0 + 4]);
                al[mi][3] = __float_as_uint(Al[r0 + 8][c0 + 4]);
            }
#pragma unroll
            for (int ni = 0; ni < 4; ++ni) {
                int c0 = wn * 32 + ni * 8 + g;
                int r0 = ks * 8 + tg;
                bh[ni][0] = __float_as_uint(Bh[r0][c0]);
                bh[ni][1] = __float_as_uint(Bh[r0 + 4][c0]);
                bl[ni][0] = __float_as_uint(Bl[r0][c0]);
                bl[ni][1] = __float_as_uint(Bl[r0 + 4][c0]);
            }
#pragma unroll
            for (int mi = 0; mi < 4; ++mi)
#pragma unroll
                for (int ni = 0; ni < 4; ++ni) {
                    mma_tf32(acc[mi][ni], ah[mi], bh[ni]);
                    mma_tf32(acc[mi][ni], al[mi], bh[ni]);
                    mma_tf32(acc[mi][ni], ah[mi], bl[ni]);
                }
        }
        __syncthreads();
        if (t + 1 < ntiles) {
            store_tile();
            __syncthreads();
        }
    }

#pragma unroll
    for (int mi = 0; mi < 4; ++mi) {
        int r0 = bm * 128 + wm * 64 + mi * 16 + g;
#pragma unroll
        for (int ni = 0; ni < 4; ++ni) {
            int c = bn * 128 + wn * 32 + ni * 8 + 2 * tg;
            float b0 = 0.f, b1 = 0.f;
            if (bias) { b0 = bias[c]; b1 = bias[c + 1]; }
            float2 o0, o1;
            o0.x = acc[mi][ni][0] + b0; o0.y = acc[mi][ni][1] + b1;
            o1.x = acc[mi][ni][2] + b0; o1.y = acc[mi][ni][3] + b1;
            *(float2*)(C + (size_t)r0 * N + c)       = o0;
            *(float2*)(C + (size_t)(r0 + 8) * N + c) = o1;
        }
    }
}

// ---------------------------------------------------------------------------
// Neox RoPE applied in-place to x[T, nheads*128].
// ---------------------------------------------------------------------------
__global__ void rope_kernel(float* __restrict__ x, const int* __restrict__ positions,
                            int Ttot, int nheads)
{
    int idx = blockIdx.x * blockDim.x + threadIdx.x;
    int total = Ttot * nheads * (HD_ / 2);
    if (idx >= total) return;
    int i = idx & 63;
    int h = (idx >> 6) % nheads;
    int t = idx / (64 * nheads);

    int pos = positions[t % S_];
    float inv_freq = powf(10000.0f, -((float)(2 * i)) / (float)HD_);
    float freq = (float)pos * inv_freq;
    float s, c;
    sincosf(freq, &s, &c);

    size_t base = (size_t)t * (nheads * HD_) + h * HD_;
    float x1 = x[base + i];
    float x2 = x[base + 64 + i];
    x[base + i]      = x1 * c - x2 * s;
    x[base + 64 + i] = x2 * c + x1 * s;
}

// ---------------------------------------------------------------------------
// Tensor-core flash attention (1xTF32 MMA, causal, GQA rep=4).
// Same algorithm as R4, but with bounded unrolling to keep ptxas cheap.
// Block: 128 threads (4 warps); each warp owns 16 query rows of a 64-row tile.
// ---------------------------------------------------------------------------
#define FB_QK_STRIDE 132
#define FB_V_STRIDE  136

__device__ __forceinline__ float quad_sel_shfl(float c0, float c1, int src, int sel) {
    float v0 = __shfl_sync(0xffffffffu, c0, src);
    float v1 = __shfl_sync(0xffffffffu, c1, src);
    return sel ? v1 : v0;
}

__global__ __launch_bounds__(128) void flash_attn_tc_kernel(
    const float* __restrict__ Q, const float* __restrict__ K,
    const float* __restrict__ V, float* __restrict__ O)
{
    extern __shared__ float sm[];
    float* sQ = sm;                                  // 64*132
    float* sK = sQ + 64 * FB_QK_STRIDE;              // 64*132
    float* sV = sK + 64 * FB_QK_STRIDE;              // 64*136

    const int qt = blockIdx.x;
    const int h  = blockIdx.y;
    const int b  = blockIdx.z;
    const int kvh = h >> 2;

    const int tid  = threadIdx.x;
    const int warp = tid >> 5;
    const int lane = tid & 31;
    const int g    = lane >> 2;   // 0..7
    const int tg   = lane & 3;    // 0..3
    const int q0   = qt * 64;
    const int w16  = warp * 16;

    const float* Qbase = Q + (size_t)b * S_ * (NH_ * HD_)  + h * HD_;
    const float* Kbase = K + (size_t)b * S_ * (NKV_ * HD_) + kvh * HD_;
    const float* Vbase = V + (size_t)b * S_ * (NKV_ * HD_) + kvh * HD_;

    // Load + tf32-convert Q tile (64 rows x 128 dims)
#pragma unroll 4
    for (int i = 0; i < 16; ++i) {
        int lin = i * 128 + tid;
        int r   = lin >> 5;
        int d4  = (lin & 31) * 4;
        float4 v = *(const float4*)(Qbase + (size_t)(q0 + r) * (NH_ * HD_) + d4);
        v.x = f2tf32(v.x); v.y = f2tf32(v.y); v.z = f2tf32(v.z); v.w = f2tf32(v.w);
        *(float4*)(sQ + r * FB_QK_STRIDE + d4) = v;
    }

    float oacc[16][4];
#pragma unroll
    for (int n = 0; n < 16; ++n)
#pragma unroll
        for (int r = 0; r < 4; ++r) oacc[n][r] = 0.f;
    float m_i[2] = { -1e30f, -1e30f };
    float l_i[2] = { 0.f, 0.f };

    __syncthreads();

    for (int j = 0; j <= qt; ++j) {
        const int k0 = j * 64;

        // Load + tf32-convert K and V tiles
#pragma unroll 4
        for (int i = 0; i < 16; ++i) {
            int lin = i * 128 + tid;
            int r   = lin >> 5;
            int d4  = (lin & 31) * 4;
            float4 kv = *(const float4*)(Kbase + (size_t)(k0 + r) * (NKV_ * HD_) + d4);
            kv.x = f2tf32(kv.x); kv.y = f2tf32(kv.y); kv.z = f2tf32(kv.z); kv.w = f2tf32(kv.w);
            *(float4*)(sK + r * FB_QK_STRIDE + d4) = kv;
            float4 vv = *(const float4*)(Vbase + (size_t)(k0 + r) * (NKV_ * HD_) + d4);
            vv.x = f2tf32(vv.x); vv.y = f2tf32(vv.y); vv.z = f2tf32(vv.z); vv.w = f2tf32(vv.w);
            *(float4*)(sV + r * FB_V_STRIDE + d4) = vv;
        }
        __syncthreads();

        // ---- S = Q @ K^T (warp computes 16x64) ----
        float sacc[8][4];
#pragma unroll
        for (int n = 0; n < 8; ++n)
#pragma unroll
            for (int r = 0; r < 4; ++r) sacc[n][r] = 0.f;

#pragma unroll 2
        for (int ks = 0; ks < 16; ++ks) {
            uint32_t a[4];
            const int kc = ks * 8 + tg;
            a[0] = __float_as_uint(sQ[(w16 + g)     * FB_QK_STRIDE + kc]);
            a[1] = __float_as_uint(sQ[(w16 + g + 8) * FB_QK_STRIDE + kc]);
            a[2] = __float_as_uint(sQ[(w16 + g)     * FB_QK_STRIDE + kc + 4]);
            a[3] = __float_as_uint(sQ[(w16 + g + 8) * FB_QK_STRIDE + kc + 4]);
#pragma unroll
            for (int n = 0; n < 8; ++n) {
                uint32_t bfr[2];
                bfr[0] = __float_as_uint(sK[(n * 8 + g) * FB_QK_STRIDE + kc]);
                bfr[1] = __float_as_uint(sK[(n * 8 + g) * FB_QK_STRIDE + kc + 4]);
                mma_tf32(sacc[n], a, bfr);
            }
        }

        // ---- scale + causal mask ----
        const int r0g = q0 + w16 + g;
        const int r1g = r0g + 8;
        const bool diag = (j == qt);
#pragma unroll
        for (int n = 0; n < 8; ++n) {
            int cb = k0 + n * 8 + 2 * tg;
            float s0 = sacc[n][0] * SCALE_;
            float s1 = sacc[n][1] * SCALE_;
            float s2 = sacc[n][2] * SCALE_;
            float s3 = sacc[n][3] * SCALE_;
            if (diag) {
                if (cb     > r0g) s0 = -1e30f;
                if (cb + 1 > r0g) s1 = -1e30f;
                if (cb     > r1g) s2 = -1e30f;
                if (cb + 1 > r1g) s3 = -1e30f;
            }
            sacc[n][0] = s0; sacc[n][1] = s1; sacc[n][2] = s2; sacc[n][3] = s3;
        }

        // ---- online softmax ----
        float mx0 = -1e30f, mx1 = -1e30f;
#pragma unroll
        for (int n = 0; n < 8; ++n) {
            mx0 = fmaxf(mx0, fmaxf(sacc[n][0], sacc[n][1]));
            mx1 = fmaxf(mx1, fmaxf(sacc[n][2], sacc[n][3]));
        }
        mx0 = fmaxf(mx0, __shfl_xor_sync(0xffffffffu, mx0, 1));
        mx0 = fmaxf(mx0, __shfl_xor_sync(0xffffffffu, mx0, 2));
        mx1 = fmaxf(mx1, __shfl_xor_sync(0xffffffffu, mx1, 1));
        mx1 = fmaxf(mx1, __shfl_xor_sync(0xffffffffu, mx1, 2));

        float mn0 = fmaxf(m_i[0], mx0);
        float mn1 = fmaxf(m_i[1], mx1);
        float al0 = __expf(m_i[0] - mn0);
        float al1 = __expf(m_i[1] - mn1);
        m_i[0] = mn0; m_i[1] = mn1;

        float rs0 = 0.f, rs1 = 0.f;
#pragma unroll
        for (int n = 0; n < 8; ++n) {
            float p0 = __expf(sacc[n][0] - mn0);
            float p1 = __expf(sacc[n][1] - mn0);
            float p2 = __expf(sacc[n][2] - mn1);
            float p3 = __expf(sacc[n][3] - mn1);
            rs0 += p0 + p1;
            rs1 += p2 + p3;
            sacc[n][0] = f2tf32(p0); sacc[n][1] = f2tf32(p1);
            sacc[n][2] = f2tf32(p2); sacc[n][3] = f2tf32(p3);
        }
        rs0 += __shfl_xor_sync(0xffffffffu, rs0, 1);
        rs0 += __shfl_xor_sync(0xffffffffu, rs0, 2);
        rs1 += __shfl_xor_sync(0xffffffffu, rs1, 1);
        rs1 += __shfl_xor_sync(0xffffffffu, rs1, 2);
        l_i[0] = l_i[0] * al0 + rs0;
        l_i[1] = l_i[1] * al1 + rs1;

        // rescale O accumulator
#pragma unroll
        for (int n = 0; n < 16; ++n) {
            oacc[n][0] *= al0; oacc[n][1] *= al0;
            oacc[n][2] *= al1; oacc[n][3] *= al1;
        }

        // ---- O += P @ V ----
        const int s0l = (g << 2) + (tg >> 1);
        const int s1l = s0l + 2;
        const int sel = tg & 1;
#pragma unroll 2
        for (int ks = 0; ks < 8; ++ks) {
            uint32_t a[4];
            a[0] = __float_as_uint(quad_sel_shfl(sacc[ks][0], sacc[ks][1], s0l, sel));
            a[1] = __float_as_uint(quad_sel_shfl(sacc[ks][2], sacc[ks][3], s0l, sel));
            a[2] = __float_as_uint(quad_sel_shfl(sacc[ks][0], sacc[ks][1], s1l, sel));
            a[3] = __float_as_uint(quad_sel_shfl(sacc[ks][2], sacc[ks][3], s1l, sel));
            const int kr0 = (ks * 8 + tg) * FB_V_STRIDE;
            const int kr1 = (ks * 8 + tg + 4) * FB_V_STRIDE;
#pragma unroll 8
            for (int n = 0; n < 16; ++n) {
                uint32_t bfr[2];
                bfr[0] = __float_as_uint(sV[kr0 + n * 8 + g]);
                bfr[1] = __float_as_uint(sV[kr1 + n * 8 + g]);
                mma_tf32(oacc[n], a, bfr);
            }
        }
        __syncthreads();   // protect sK/sV before next iteration
    }

    // ---- epilogue: divide by l, write out ----
    float inv0 = 1.0f / l_i[0];
    float inv1 = 1.0f / l_i[1];
    size_t t0 = (size_t)b * S_ + q0 + w16 + g;
    size_t t1 = t0 + 8;
    float* op0 = O + t0 * (NH_ * HD_) + h * HD_;
    float* op1 = O + t1 * (NH_ * HD_) + h * HD_;
#pragma unroll
    for (int n = 0; n < 16; ++n) {
        int c = n * 8 + 2 * tg;
        float2 v0, v1;
        v0.x = oacc[n][0] * inv0; v0.y = oacc[n][1] * inv0;
        v1.x = oacc[n][2] * inv1; v1.y = oacc[n][3] * inv1;
        *(float2*)(op0 + c) = v0;
        *(float2*)(op1 + c) = v1;
    }
}

// ---------------------------------------------------------------------------
// Launch
// ---------------------------------------------------------------------------
extern "C" void kernel_launch(void* const* d_in, const int* in_sizes, int n_in,
                              void* d_out, int out_size)
{
    const float* hidden = (const float*)d_in[0];
    const int*   positions = (const int*)d_in[1];
    const float* Wq = (const float*)d_in[2];
    const float* bq = (const float*)d_in[3];
    const float* Wk = (const float*)d_in[4];
    const float* bk = (const float*)d_in[5];
    const float* Wv = (const float*)d_in[6];
    const float* bv = (const float*)d_in[7];
    const float* Wo = (const float*)d_in[8];
    float* out = (float*)d_out;

    void *pQ, *pK, *pV, *pA;
    cudaGetSymbolAddress(&pQ, g_Q);
    cudaGetSymbolAddress(&pK, g_K);
    cudaGetSymbolAddress(&pV, g_V);
    cudaGetSymbolAddress(&pA, g_ATTN);
    float* Qs = (float*)pQ;
    float* Ks = (float*)pK;
    float* Vs = (float*)pV;
    float* As = (float*)pA;

    // QKV projections (tensor cores, 3xTF32)
    tf32_gemm_kernel<<<dim3((NH_ * HD_) / 128, T_ / 128), 256>>>(hidden, Wq, bq, Qs, T_, NH_ * HD_, H_);
    tf32_gemm_kernel<<<dim3((NKV_ * HD_) / 128, T_ / 128), 256>>>(hidden, Wk, bk, Ks, T_, NKV_ * HD_, H_);
    tf32_gemm_kernel<<<dim3((NKV_ * HD_) / 128, T_ / 128), 256>>>(hidden, Wv, bv, Vs, T_, NKV_ * HD_, H_);

    // RoPE on Q and K
    {
        int totq = T_ * NH_ * 64;
        rope_kernel<<<(totq + 255) / 256, 256>>>(Qs, positions, T_, NH_);
        int totk = T_ * NKV_ * 64;
        rope_kernel<<<(totk + 255) / 256, 256>>>(Ks, positions, T_, NKV_);
    }

    // Tensor-core flash attention
    size_t fa_smem = (size_t)(64 * FB_QK_STRIDE * 2 + 64 * FB_V_STRIDE) * sizeof(float);
    cudaFuncSetAttribute(flash_attn_tc_kernel, cudaFuncAttributeMaxDynamicSharedMemorySize, (int)fa_smem);
    flash_attn_tc_kernel<<<dim3(S_ / 64, NH_, B_), 128, fa_smem>>>(Qs, Ks, Vs, As);

    // Output projection (tensor cores, 3xTF32)
    tf32_gemm_kernel<<<dim3(H_ / 128, T_ / 128), 256>>>(As, Wo, nullptr, out, T_, H_, NH_ * HD_);
}

// round 8
// speedup vs baseline: 1.6238x; 1.2387x over previous
#include <cuda_runtime.h>
#include <cuda_bf16.h>
#include <math.h>
#include <stdint.h>

// Problem constants (fixed for this problem instance)
#define B_   2
#define S_   2048
#define H_   2048
#define NH_  16
#define NKV_ 4
#define HD_  128
#define T_   (B_ * S_)            // 4096 tokens
#define SCALE_ 0.08838834764831845f   // 128^-0.5

// ---------------------------------------------------------------------------
// Device scratch (allocation-free rule: __device__ globals)
// ---------------------------------------------------------------------------
__device__ float g_Q[T_ * NH_ * HD_];      // [4096, 2048]
__device__ float g_K[T_ * NKV_ * HD_];     // [4096, 512]
__device__ float g_V[T_ * NKV_ * HD_];     // [4096, 512]
__device__ float g_ATTN[T_ * NH_ * HD_];   // [4096, 2048]

// ---------------------------------------------------------------------------
// Numeric helpers
// ---------------------------------------------------------------------------
__device__ __forceinline__ uint32_t f2tf32_bits(float x) {
    uint32_t y;
    asm("cvt.rna.tf32.f32 %0, %1;" : "=r"(y) : "f"(x));
    return y;
}
__device__ __forceinline__ float f2tf32(float x) {
    return __uint_as_float(f2tf32_bits(x));
}
__device__ __forceinline__ void mma_tf32(float* d, const uint32_t* a, const uint32_t* b) {
    asm volatile(
        "mma.sync.aligned.m16n8k8.row.col.f32.tf32.tf32.f32 "
        "{%0,%1,%2,%3}, {%4,%5,%6,%7}, {%8,%9}, {%0,%1,%2,%3};"
        : "+f"(d[0]), "+f"(d[1]), "+f"(d[2]), "+f"(d[3])
        : "r"(a[0]), "r"(a[1]), "r"(a[2]), "r"(a[3]), "r"(b[0]), "r"(b[1]));
}
__device__ __forceinline__ void mma_bf16(float* d, const uint32_t* a, const uint32_t* b) {
    asm volatile(
        "mma.sync.aligned.m16n8k16.row.col.f32.bf16.bf16.f32 "
        "{%0,%1,%2,%3}, {%4,%5,%6,%7}, {%8,%9}, {%0,%1,%2,%3};"
        : "+f"(d[0]), "+f"(d[1]), "+f"(d[2]), "+f"(d[3])
        : "r"(a[0]), "r"(a[1]), "r"(a[2]), "r"(a[3]), "r"(b[0]), "r"(b[1]));
}
__device__ __forceinline__ void split_bf16(float x, float& h, float& l) {
    __nv_bfloat16 hb = __float2bfloat16_rn(x);
    h = __bfloat162float(hb);
    l = x - h;
}
__device__ __forceinline__ uint32_t bf16x2(float x, float y) {
    __nv_bfloat162 t = __floats2bfloat162_rn(x, y);   // x -> low half (even k)
    return *reinterpret_cast<uint32_t*>(&t);
}

// ---------------------------------------------------------------------------
// Split-BF16 tensor-core GEMM (hi/lo, 3 MMAs m16n8k16) — ~fp32-accurate.
// C[M,N] = A[M,K] @ B[K,N] (+ bias[N]); row-major. Tile 128x128x16.
// 256 threads (8 warps as 2x4), warp tile 64x32.
// SMEM rows padded to 12 words: bank pattern (12g+tg) mod 32 conflict-free.
// ---------------------------------------------------------------------------
#define GB_STRIDE 12

__global__ __launch_bounds__(256) void bf16_gemm_kernel(
    const float* __restrict__ A, const float* __restrict__ Bm,
    const float* __restrict__ bias, float* __restrict__ C,
    int M, int N, int K)
{
    __shared__ uint32_t Ah[128 * GB_STRIDE];
    __shared__ uint32_t Al[128 * GB_STRIDE];
    __shared__ uint32_t Bh[128 * GB_STRIDE];
    __shared__ uint32_t Bl[128 * GB_STRIDE];

    const int tid  = threadIdx.x;
    const int warp = tid >> 5;
    const int lane = tid & 31;
    const int g    = lane >> 2;   // 0..7
    const int tg   = lane & 3;    // 0..3
    const int wm   = warp >> 2;   // 0..1
    const int wn   = warp & 3;    // 0..3

    const int bm = blockIdx.y;
    const int bn = blockIdx.x;

    const float* Ab = A + (size_t)(bm * 128) * K;
    const float* Bb = Bm + bn * 128;

    float acc[4][4][4];
#pragma unroll
    for (int mi = 0; mi < 4; ++mi)
#pragma unroll
        for (int ni = 0; ni < 4; ++ni)
#pragma unroll
            for (int r = 0; r < 4; ++r) acc[mi][ni][r] = 0.f;

    float2 aReg[4];
    float  bReg[4][2];

    // A pairs: p -> (row = p>>3, k2 = p&7); B pairs: p -> (k2 = (p>>7)&7, n = p&127)
    auto load_tile = [&](int k0) {
#pragma unroll
        for (int i = 0; i < 4; ++i) {
            int p  = i * 256 + tid;
            int ar = p >> 3, ak = p & 7;
            aReg[i] = *(const float2*)(Ab + (size_t)ar * K + k0 + 2 * ak);
            int bk = (p >> 7) & 7, bnn = p & 127;
            bReg[i][0] = Bb[(size_t)(k0 + 2 * bk)     * N + bnn];
            bReg[i][1] = Bb[(size_t)(k0 + 2 * bk + 1) * N + bnn];
        }
    };
    auto store_tile = [&]() {
#pragma unroll
        for (int i = 0; i < 4; ++i) {
            int p  = i * 256 + tid;
            int ar = p >> 3, ak = p & 7;
            float hx, lx, hy, ly;
            split_bf16(aReg[i].x, hx, lx);
            split_bf16(aReg[i].y, hy, ly);
            Ah[ar * GB_STRIDE + ak] = bf16x2(hx, hy);
            Al[ar * GB_STRIDE + ak] = bf16x2(lx, ly);
            int bk = (p >> 7) & 7, bnn = p & 127;
            float h0, l0, h1, l1;
            split_bf16(bReg[i][0], h0, l0);
            split_bf16(bReg[i][1], h1, l1);
            Bh[bnn * GB_STRIDE + bk] = bf16x2(h0, h1);
            Bl[bnn * GB_STRIDE + bk] = bf16x2(l0, l1);
        }
    };

    const int ntiles = K / 16;

    load_tile(0);
    store_tile();
    __syncthreads();

    for (int t = 0; t < ntiles; ++t) {
        if (t + 1 < ntiles) load_tile((t + 1) * 16);

        uint32_t ah[4][4], al[4][4];
        uint32_t bh[4][2], bl[4][2];
#pragma unroll
        for (int mi = 0; mi < 4; ++mi) {
            int r0 = (wm * 64 + mi * 16 + g) * GB_STRIDE;
            ah[mi][0] = Ah[r0 + tg];
            ah[mi][1] = Ah[r0 + 8 * GB_STRIDE + tg];
            ah[mi][2] = Ah[r0 + tg + 4];
            ah[mi][3] = Ah[r0 + 8 * GB_STRIDE + tg + 4];
            al[mi][0] = Al[r0 + tg];
            al[mi][1] = Al[r0 + 8 * GB_STRIDE + tg];
            al[mi][2] = Al[r0 + tg + 4];
            al[mi][3] = Al[r0 + 8 * GB_STRIDE + tg + 4];
        }
#pragma unroll
        for (int ni = 0; ni < 4; ++ni) {
            int n0 = (wn * 32 + ni * 8 + g) * GB_STRIDE;
            bh[ni][0] = Bh[n0 + tg];
            bh[ni][1] = Bh[n0 + tg + 4];
            bl[ni][0] = Bl[n0 + tg];
            bl[ni][1] = Bl[n0 + tg + 4];
        }
#pragma unroll
        for (int mi = 0; mi < 4; ++mi)
#pragma unroll
            for (int ni = 0; ni < 4; ++ni) {
                mma_bf16(acc[mi][ni], ah[mi], bh[ni]);
                mma_bf16(acc[mi][ni], al[mi], bh[ni]);
                mma_bf16(acc[mi][ni], ah[mi], bl[ni]);
            }
        __syncthreads();
        if (t + 1 < ntiles) {
            store_tile();
            __syncthreads();
        }
    }

    // Epilogue: add bias, write out
#pragma unroll
    for (int mi = 0; mi < 4; ++mi) {
        int r0 = bm * 128 + wm * 64 + mi * 16 + g;
#pragma unroll
        for (int ni = 0; ni < 4; ++ni) {
            int c = bn * 128 + wn * 32 + ni * 8 + 2 * tg;
            float b0 = 0.f, b1 = 0.f;
            if (bias) { b0 = bias[c]; b1 = bias[c + 1]; }
            float2 o0, o1;
            o0.x = acc[mi][ni][0] + b0; o0.y = acc[mi][ni][1] + b1;
            o1.x = acc[mi][ni][2] + b0; o1.y = acc[mi][ni][3] + b1;
            *(float2*)(C + (size_t)r0 * N + c)       = o0;
            *(float2*)(C + (size_t)(r0 + 8) * N + c) = o1;
        }
    }
}

// ---------------------------------------------------------------------------
// Neox RoPE applied in-place to x[T, nheads*128].
// ---------------------------------------------------------------------------
__global__ void rope_kernel(float* __restrict__ x, const int* __restrict__ positions,
                            int Ttot, int nheads)
{
    int idx = blockIdx.x * blockDim.x + threadIdx.x;
    int total = Ttot * nheads * (HD_ / 2);
    if (idx >= total) return;
    int i = idx & 63;
    int h = (idx >> 6) % nheads;
    int t = idx / (64 * nheads);

    int pos = positions[t % S_];
    float inv_freq = powf(10000.0f, -((float)(2 * i)) / (float)HD_);
    float freq = (float)pos * inv_freq;
    float s, c;
    sincosf(freq, &s, &c);

    size_t base = (size_t)t * (nheads * HD_) + h * HD_;
    float x1 = x[base + i];
    float x2 = x[base + 64 + i];
    x[base + i]      = x1 * c - x2 * s;
    x[base + 64 + i] = x2 * c + x1 * s;
}

// ---------------------------------------------------------------------------
// Tensor-core flash attention (1xTF32 MMA, causal, GQA rep=4).
// EXACTLY the R6-passing version: 128 threads (4 warps), BM=64.
// ---------------------------------------------------------------------------
#define FB_QK_STRIDE 132
#define FB_V_STRIDE  136

__device__ __forceinline__ float quad_sel_shfl(float c0, float c1, int src, int sel) {
    float v0 = __shfl_sync(0xffffffffu, c0, src);
    float v1 = __shfl_sync(0xffffffffu, c1, src);
    return sel ? v1 : v0;
}

__global__ __launch_bounds__(128) void flash_attn_tc_kernel(
    const float* __restrict__ Q, const float* __restrict__ K,
    const float* __restrict__ V, float* __restrict__ O)
{
    extern __shared__ float sm[];
    float* sQ = sm;                                  // 64*132
    float* sK = sQ + 64 * FB_QK_STRIDE;              // 64*132
    float* sV = sK + 64 * FB_QK_STRIDE;              // 64*136

    const int qt = blockIdx.x;
    const int h  = blockIdx.y;
    const int b  = blockIdx.z;
    const int kvh = h >> 2;

    const int tid  = threadIdx.x;
    const int warp = tid >> 5;
    const int lane = tid & 31;
    const int g    = lane >> 2;   // 0..7
    const int tg   = lane & 3;    // 0..3
    const int q0   = qt * 64;
    const int w16  = warp * 16;

    const float* Qbase = Q + (size_t)b * S_ * (NH_ * HD_)  + h * HD_;
    const float* Kbase = K + (size_t)b * S_ * (NKV_ * HD_) + kvh * HD_;
    const float* Vbase = V + (size_t)b * S_ * (NKV_ * HD_) + kvh * HD_;

    // Load + tf32-convert Q tile (64 rows x 128 dims)
#pragma unroll 4
    for (int i = 0; i < 16; ++i) {
        int lin = i * 128 + tid;
        int r   = lin >> 5;
        int d4  = (lin & 31) * 4;
        float4 v = *(const float4*)(Qbase + (size_t)(q0 + r) * (NH_ * HD_) + d4);
        v.x = f2tf32(v.x); v.y = f2tf32(v.y); v.z = f2tf32(v.z); v.w = f2tf32(v.w);
        *(float4*)(sQ + r * FB_QK_STRIDE + d4) = v;
    }

    float oacc[16][4];
#pragma unroll
    for (int n = 0; n < 16; ++n)
#pragma unroll
        for (int r = 0; r < 4; ++r) oacc[n][r] = 0.f;
    float m_i[2] = { -1e30f, -1e30f };
    float l_i[2] = { 0.f, 0.f };

    __syncthreads();

    for (int j = 0; j <= qt; ++j) {
        const int k0 = j * 64;

        // Load + tf32-convert K and V tiles
#pragma unroll 4
        for (int i = 0; i < 16; ++i) {
            int lin = i * 128 + tid;
            int r   = lin >> 5;
            int d4  = (lin & 31) * 4;
            float4 kv = *(const float4*)(Kbase + (size_t)(k0 + r) * (NKV_ * HD_) + d4);
            kv.x = f2tf32(kv.x); kv.y = f2tf32(kv.y); kv.z = f2tf32(kv.z); kv.w = f2tf32(kv.w);
            *(float4*)(sK + r * FB_QK_STRIDE + d4) = kv;
            float4 vv = *(const float4*)(Vbase + (size_t)(k0 + r) * (NKV_ * HD_) + d4);
            vv.x = f2tf32(vv.x); vv.y = f2tf32(vv.y); vv.z = f2tf32(vv.z); vv.w = f2tf32(vv.w);
            *(float4*)(sV + r * FB_V_STRIDE + d4) = vv;
        }
        __syncthreads();

        // ---- S = Q @ K^T (warp computes 16x64) ----
        float sacc[8][4];
#pragma unroll
        for (int n = 0; n < 8; ++n)
#pragma unroll
            for (int r = 0; r < 4; ++r) sacc[n][r] = 0.f;

#pragma unroll 2
        for (int ks = 0; ks < 16; ++ks) {
            uint32_t a[4];
            const int kc = ks * 8 + tg;
            a[0] = __float_as_uint(sQ[(w16 + g)     * FB_QK_STRIDE + kc]);
            a[1] = __float_as_uint(sQ[(w16 + g + 8) * FB_QK_STRIDE + kc]);
            a[2] = __float_as_uint(sQ[(w16 + g)     * FB_QK_STRIDE + kc + 4]);
            a[3] = __float_as_uint(sQ[(w16 + g + 8) * FB_QK_STRIDE + kc + 4]);
#pragma unroll
            for (int n = 0; n < 8; ++n) {
                uint32_t bfr[2];
                bfr[0] = __float_as_uint(sK[(n * 8 + g) * FB_QK_STRIDE + kc]);
                bfr[1] = __float_as_uint(sK[(n * 8 + g) * FB_QK_STRIDE + kc + 4]);
                mma_tf32(sacc[n], a, bfr);
            }
        }

        // ---- scale + causal mask ----
        const int r0g = q0 + w16 + g;
        const int r1g = r0g + 8;
        const bool diag = (j == qt);
#pragma unroll
        for (int n = 0; n < 8; ++n) {
            int cb = k0 + n * 8 + 2 * tg;
            float s0 = sacc[n][0] * SCALE_;
            float s1 = sacc[n][1] * SCALE_;
            float s2 = sacc[n][2] * SCALE_;
            float s3 = sacc[n][3] * SCALE_;
            if (diag) {
                if (cb     > r0g) s0 = -1e30f;
                if (cb + 1 > r0g) s1 = -1e30f;
                if (cb     > r1g) s2 = -1e30f;
                if (cb + 1 > r1g) s3 = -1e30f;
            }
            sacc[n][0] = s0; sacc[n][1] = s1; sacc[n][2] = s2; sacc[n][3] = s3;
        }

        // ---- online softmax ----
        float mx0 = -1e30f, mx1 = -1e30f;
#pragma unroll
        for (int n = 0; n < 8; ++n) {
            mx0 = fmaxf(mx0, fmaxf(sacc[n][0], sacc[n][1]));
            mx1 = fmaxf(mx1, fmaxf(sacc[n][2], sacc[n][3]));
        }
        mx0 = fmaxf(mx0, __shfl_xor_sync(0xffffffffu, mx0, 1));
        mx0 = fmaxf(mx0, __shfl_xor_sync(0xffffffffu, mx0, 2));
        mx1 = fmaxf(mx1, __shfl_xor_sync(0xffffffffu, mx1, 1));
        mx1 = fmaxf(mx1, __shfl_xor_sync(0xffffffffu, mx1, 2));

        float mn0 = fmaxf(m_i[0], mx0);
        float mn1 = fmaxf(m_i[1], mx1);
        float al0 = __expf(m_i[0] - mn0);
        float al1 = __expf(m_i[1] - mn1);
        m_i[0] = mn0; m_i[1] = mn1;

        float rs0 = 0.f, rs1 = 0.f;
#pragma unroll
        for (int n = 0; n < 8; ++n) {
            float p0 = __expf(sacc[n][0] - mn0);
            float p1 = __expf(sacc[n][1] - mn0);
            float p2 = __expf(sacc[n][2] - mn1);
            float p3 = __expf(sacc[n][3] - mn1);
            rs0 += p0 + p1;
            rs1 += p2 + p3;
            sacc[n][0] = f2tf32(p0); sacc[n][1] = f2tf32(p1);
            sacc[n][2] = f2tf32(p2); sacc[n][3] = f2tf32(p3);
        }
        rs0 += __shfl_xor_sync(0xffffffffu, rs0, 1);
        rs0 += __shfl_xor_sync(0xffffffffu, rs0, 2);
        rs1 += __shfl_xor_sync(0xffffffffu, rs1, 1);
        rs1 += __shfl_xor_sync(0xffffffffu, rs1, 2);
        l_i[0] = l_i[0] * al0 + rs0;
        l_i[1] = l_i[1] * al1 + rs1;

        // rescale O accumulator
#pragma unroll
        for (int n = 0; n < 16; ++n) {
            oacc[n][0] *= al0; oacc[n][1] *= al0;
            oacc[n][2] *= al1; oacc[n][3] *= al1;
        }

        // ---- O += P @ V ----
        const int s0l = (g << 2) + (tg >> 1);
        const int s1l = s0l + 2;
        const int sel = tg & 1;
#pragma unroll 2
        for (int ks = 0; ks < 8; ++ks) {
            uint32_t a[4];
            a[0] = __float_as_uint(quad_sel_shfl(sacc[ks][0], sacc[ks][1], s0l, sel));
            a[1] = __float_as_uint(quad_sel_shfl(sacc[ks][2], sacc[ks][3], s0l, sel));
            a[2] = __float_as_uint(quad_sel_shfl(sacc[ks][0], sacc[ks][1], s1l, sel));
            a[3] = __float_as_uint(quad_sel_shfl(sacc[ks][2], sacc[ks][3], s1l, sel));
            const int kr0 = (ks * 8 + tg) * FB_V_STRIDE;
            const int kr1 = (ks * 8 + tg + 4) * FB_V_STRIDE;
#pragma unroll 8
            for (int n = 0; n < 16; ++n) {
                uint32_t bfr[2];
                bfr[0] = __float_as_uint(sV[kr0 + n * 8 + g]);
                bfr[1] = __float_as_uint(sV[kr1 + n * 8 + g]);
                mma_tf32(oacc[n], a, bfr);
            }
        }
        __syncthreads();   // protect sK/sV before next iteration
    }

    // ---- epilogue: divide by l, write out ----
    float inv0 = 1.0f / l_i[0];
    float inv1 = 1.0f / l_i[1];
    size_t t0 = (size_t)b * S_ + q0 + w16 + g;
    size_t t1 = t0 + 8;
    float* op0 = O + t0 * (NH_ * HD_) + h * HD_;
    float* op1 = O + t1 * (NH_ * HD_) + h * HD_;
#pragma unroll
    for (int n = 0; n < 16; ++n) {
        int c = n * 8 + 2 * tg;
        float2 v0, v1;
        v0.x = oacc[n][0] * inv0; v0.y = oacc[n][1] * inv0;
        v1.x = oacc[n][2] * inv1; v1.y = oacc[n][3] * inv1;
        *(float2*)(op0 + c) = v0;
        *(float2*)(op1 + c) = v1;
    }
}

// ---------------------------------------------------------------------------
// Launch
// ---------------------------------------------------------------------------
extern "C" void kernel_launch(void* const* d_in, const int* in_sizes, int n_in,
                              void* d_out, int out_size)
{
    const float* hidden = (const float*)d_in[0];
    const int*   positions = (const int*)d_in[1];
    const float* Wq = (const float*)d_in[2];
    const float* bq = (const float*)d_in[3];
    const float* Wk = (const float*)d_in[4];
    const float* bk = (const float*)d_in[5];
    const float* Wv = (const float*)d_in[6];
    const float* bv = (const float*)d_in[7];
    const float* Wo = (const float*)d_in[8];
    float* out = (float*)d_out;

    void *pQ, *pK, *pV, *pA;
    cudaGetSymbolAddress(&pQ, g_Q);
    cudaGetSymbolAddress(&pK, g_K);
    cudaGetSymbolAddress(&pV, g_V);
    cudaGetSymbolAddress(&pA, g_ATTN);
    float* Qs = (float*)pQ;
    float* Ks = (float*)pK;
    float* Vs = (float*)pV;
    float* As = (float*)pA;

    // QKV projections (tensor cores, split-bf16)
    bf16_gemm_kernel<<<dim3((NH_ * HD_) / 128, T_ / 128), 256>>>(hidden, Wq, bq, Qs, T_, NH_ * HD_, H_);
    bf16_gemm_kernel<<<dim3((NKV_ * HD_) / 128, T_ / 128), 256>>>(hidden, Wk, bk, Ks, T_, NKV_ * HD_, H_);
    bf16_gemm_kernel<<<dim3((NKV_ * HD_) / 128, T_ / 128), 256>>>(hidden, Wv, bv, Vs, T_, NKV_ * HD_, H_);

    // RoPE on Q and K
    {
        int totq = T_ * NH_ * 64;
        rope_kernel<<<(totq + 255) / 256, 256>>>(Qs, positions, T_, NH_);
        int totk = T_ * NKV_ * 64;
        rope_kernel<<<(totk + 255) / 256, 256>>>(Ks, positions, T_, NKV_);
    }

    // Tensor-core flash attention (R6-passing version: BM=64, 4 warps)
    size_t fa_smem = (size_t)(64 * FB_QK_STRIDE * 2 + 64 * FB_V_STRIDE) * sizeof(float);
    cudaFuncSetAttribute(flash_attn_tc_kernel, cudaFuncAttributeMaxDynamicSharedMemorySize, (int)fa_smem);
    flash_attn_tc_kernel<<<dim3(S_ / 64, NH_, B_), 128, fa_smem>>>(Qs, Ks, Vs, As);

    // Output projection (tensor cores, split-bf16)
    bf16_gemm_kernel<<<dim3(H_ / 128, T_ / 128), 256>>>(As, Wo, nullptr, out, T_, H_, NH_ * HD_);
}

// round 9
// speedup vs baseline: 1.7052x; 1.0501x over previous
#include <cuda_runtime.h>
#include <cuda_bf16.h>
#include <math.h>
#include <stdint.h>

// Problem constants (fixed for this problem instance)
#define B_   2
#define S_   2048
#define H_   2048
#define NH_  16
#define NKV_ 4
#define HD_  128
#define T_   (B_ * S_)            // 4096 tokens
#define SCALE_ 0.08838834764831845f   // 128^-0.5

// ---------------------------------------------------------------------------
// Device scratch (allocation-free rule: __device__ globals)
// ---------------------------------------------------------------------------
__device__ float g_Q[T_ * NH_ * HD_];      // [4096, 2048]
__device__ float g_K[T_ * NKV_ * HD_];     // [4096, 512]
__device__ float g_V[T_ * NKV_ * HD_];     // [4096, 512]
__device__ float g_ATTN[T_ * NH_ * HD_];   // [4096, 2048]

// ---------------------------------------------------------------------------
// Numeric helpers
// ---------------------------------------------------------------------------
__device__ __forceinline__ uint32_t f2tf32_bits(float x) {
    uint32_t y;
    asm("cvt.rna.tf32.f32 %0, %1;" : "=r"(y) : "f"(x));
    return y;
}
__device__ __forceinline__ float f2tf32(float x) {
    return __uint_as_float(f2tf32_bits(x));
}
__device__ __forceinline__ void mma_tf32(float* d, const uint32_t* a, const uint32_t* b) {
    asm volatile(
        "mma.sync.aligned.m16n8k8.row.col.f32.tf32.tf32.f32 "
        "{%0,%1,%2,%3}, {%4,%5,%6,%7}, {%8,%9}, {%0,%1,%2,%3};"
        : "+f"(d[0]), "+f"(d[1]), "+f"(d[2]), "+f"(d[3])
        : "r"(a[0]), "r"(a[1]), "r"(a[2]), "r"(a[3]), "r"(b[0]), "r"(b[1]));
}
__device__ __forceinline__ void mma_bf16(float* d, const uint32_t* a, const uint32_t* b) {
    asm volatile(
        "mma.sync.aligned.m16n8k16.row.col.f32.bf16.bf16.f32 "
        "{%0,%1,%2,%3}, {%4,%5,%6,%7}, {%8,%9}, {%0,%1,%2,%3};"
        : "+f"(d[0]), "+f"(d[1]), "+f"(d[2]), "+f"(d[3])
        : "r"(a[0]), "r"(a[1]), "r"(a[2]), "r"(a[3]), "r"(b[0]), "r"(b[1]));
}
__device__ __forceinline__ void split_bf16(float x, float& h, float& l) {
    __nv_bfloat16 hb = __float2bfloat16_rn(x);
    h = __bfloat162float(hb);
    l = x - h;
}
__device__ __forceinline__ uint32_t bf16x2(float x, float y) {
    __nv_bfloat162 t = __floats2bfloat162_rn(x, y);   // x -> low half (even k)
    return *reinterpret_cast<uint32_t*>(&t);
}

// ---------------------------------------------------------------------------
// Split-BF16 tensor-core GEMM (hi/lo, 3 MMAs m16n8k16) — ~fp32-accurate.
// (unchanged from R8 passing version)
// ---------------------------------------------------------------------------
#define GB_STRIDE 12

__global__ __launch_bounds__(256) void bf16_gemm_kernel(
    const float* __restrict__ A, const float* __restrict__ Bm,
    const float* __restrict__ bias, float* __restrict__ C,
    int M, int N, int K)
{
    __shared__ uint32_t Ah[128 * GB_STRIDE];
    __shared__ uint32_t Al[128 * GB_STRIDE];
    __shared__ uint32_t Bh[128 * GB_STRIDE];
    __shared__ uint32_t Bl[128 * GB_STRIDE];

    const int tid  = threadIdx.x;
    const int warp = tid >> 5;
    const int lane = tid & 31;
    const int g    = lane >> 2;   // 0..7
    const int tg   = lane & 3;    // 0..3
    const int wm   = warp >> 2;   // 0..1
    const int wn   = warp & 3;    // 0..3

    const int bm = blockIdx.y;
    const int bn = blockIdx.x;

    const float* Ab = A + (size_t)(bm * 128) * K;
    const float* Bb = Bm + bn * 128;

    float acc[4][4][4];
#pragma unroll
    for (int mi = 0; mi < 4; ++mi)
#pragma unroll
        for (int ni = 0; ni < 4; ++ni)
#pragma unroll
            for (int r = 0; r < 4; ++r) acc[mi][ni][r] = 0.f;

    float2 aReg[4];
    float  bReg[4][2];

    auto load_tile = [&](int k0) {
#pragma unroll
        for (int i = 0; i < 4; ++i) {
            int p  = i * 256 + tid;
            int ar = p >> 3, ak = p & 7;
            aReg[i] = *(const float2*)(Ab + (size_t)ar * K + k0 + 2 * ak);
            int bk = (p >> 7) & 7, bnn = p & 127;
            bReg[i][0] = Bb[(size_t)(k0 + 2 * bk)     * N + bnn];
            bReg[i][1] = Bb[(size_t)(k0 + 2 * bk + 1) * N + bnn];
        }
    };
    auto store_tile = [&]() {
#pragma unroll
        for (int i = 0; i < 4; ++i) {
            int p  = i * 256 + tid;
            int ar = p >> 3, ak = p & 7;
            float hx, lx, hy, ly;
            split_bf16(aReg[i].x, hx, lx);
            split_bf16(aReg[i].y, hy, ly);
            Ah[ar * GB_STRIDE + ak] = bf16x2(hx, hy);
            Al[ar * GB_STRIDE + ak] = bf16x2(lx, ly);
            int bk = (p >> 7) & 7, bnn = p & 127;
            float h0, l0, h1, l1;
            split_bf16(bReg[i][0], h0, l0);
            split_bf16(bReg[i][1], h1, l1);
            Bh[bnn * GB_STRIDE + bk] = bf16x2(h0, h1);
            Bl[bnn * GB_STRIDE + bk] = bf16x2(l0, l1);
        }
    };

    const int ntiles = K / 16;

    load_tile(0);
    store_tile();
    __syncthreads();

    for (int t = 0; t < ntiles; ++t) {
        if (t + 1 < ntiles) load_tile((t + 1) * 16);

        uint32_t ah[4][4], al[4][4];
        uint32_t bh[4][2], bl[4][2];
#pragma unroll
        for (int mi = 0; mi < 4; ++mi) {
            int r0 = (wm * 64 + mi * 16 + g) * GB_STRIDE;
            ah[mi][0] = Ah[r0 + tg];
            ah[mi][1] = Ah[r0 + 8 * GB_STRIDE + tg];
            ah[mi][2] = Ah[r0 + tg + 4];
            ah[mi][3] = Ah[r0 + 8 * GB_STRIDE + tg + 4];
            al[mi][0] = Al[r0 + tg];
            al[mi][1] = Al[r0 + 8 * GB_STRIDE + tg];
            al[mi][2] = Al[r0 + tg + 4];
            al[mi][3] = Al[r0 + 8 * GB_STRIDE + tg + 4];
        }
#pragma unroll
        for (int ni = 0; ni < 4; ++ni) {
            int n0 = (wn * 32 + ni * 8 + g) * GB_STRIDE;
            bh[ni][0] = Bh[n0 + tg];
            bh[ni][1] = Bh[n0 + tg + 4];
            bl[ni][0] = Bl[n0 + tg];
            bl[ni][1] = Bl[n0 + tg + 4];
        }
#pragma unroll
        for (int mi = 0; mi < 4; ++mi)
#pragma unroll
            for (int ni = 0; ni < 4; ++ni) {
                mma_bf16(acc[mi][ni], ah[mi], bh[ni]);
                mma_bf16(acc[mi][ni], al[mi], bh[ni]);
                mma_bf16(acc[mi][ni], ah[mi], bl[ni]);
            }
        __syncthreads();
        if (t + 1 < ntiles) {
            store_tile();
            __syncthreads();
        }
    }

    // Epilogue: add bias, write out
#pragma unroll
    for (int mi = 0; mi < 4; ++mi) {
        int r0 = bm * 128 + wm * 64 + mi * 16 + g;
#pragma unroll
        for (int ni = 0; ni < 4; ++ni) {
            int c = bn * 128 + wn * 32 + ni * 8 + 2 * tg;
            float b0 = 0.f, b1 = 0.f;
            if (bias) { b0 = bias[c]; b1 = bias[c + 1]; }
            float2 o0, o1;
            o0.x = acc[mi][ni][0] + b0; o0.y = acc[mi][ni][1] + b1;
            o1.x = acc[mi][ni][2] + b0; o1.y = acc[mi][ni][3] + b1;
            *(float2*)(C + (size_t)r0 * N + c)       = o0;
            *(float2*)(C + (size_t)(r0 + 8) * N + c) = o1;
        }
    }
}

// ---------------------------------------------------------------------------
// Neox RoPE applied in-place to x[T, nheads*128].
// ---------------------------------------------------------------------------
__global__ void rope_kernel(float* __restrict__ x, const int* __restrict__ positions,
                            int Ttot, int nheads)
{
    int idx = blockIdx.x * blockDim.x + threadIdx.x;
    int total = Ttot * nheads * (HD_ / 2);
    if (idx >= total) return;
    int i = idx & 63;
    int h = (idx >> 6) % nheads;
    int t = idx / (64 * nheads);

    int pos = positions[t % S_];
    float inv_freq = powf(10000.0f, -((float)(2 * i)) / (float)HD_);
    float freq = (float)pos * inv_freq;
    float s, c;
    sincosf(freq, &s, &c);

    size_t base = (size_t)t * (nheads * HD_) + h * HD_;
    float x1 = x[base + i];
    float x2 = x[base + 64 + i];
    x[base + i]      = x1 * c - x2 * s;
    x[base + 64 + i] = x2 * c + x1 * s;
}

// ---------------------------------------------------------------------------
// Tensor-core flash attention (1xTF32 MMA, causal, GQA rep=4).
// Block: 256 threads (8 warps); BM=128 query rows (16 per warp), BN=64.
// SMEM: sQ[128][132], sK[64][132], sV[64][136] (tf32).
// ---------------------------------------------------------------------------
#define FB_QK_STRIDE 132
#define FB_V_STRIDE  136
#define FA_BM2 128

__device__ __forceinline__ float quad_sel_shfl(float c0, float c1, int src, int sel) {
    float v0 = __shfl_sync(0xffffffffu, c0, src);
    float v1 = __shfl_sync(0xffffffffu, c1, src);
    return sel ? v1 : v0;
}

__global__ __launch_bounds__(256) void flash_attn_tc_kernel(
    const float* __restrict__ Q, const float* __restrict__ K,
    const float* __restrict__ V, float* __restrict__ O)
{
    extern __shared__ float sm[];
    float* sQ = sm;                                   // 128*132
    float* sK = sQ + FA_BM2 * FB_QK_STRIDE;           // 64*132
    float* sV = sK + 64 * FB_QK_STRIDE;               // 64*136

    const int qt = blockIdx.x;
    const int h  = blockIdx.y;
    const int b  = blockIdx.z;
    const int kvh = h >> 2;

    const int tid  = threadIdx.x;
    const int warp = tid >> 5;
    const int lane = tid & 31;
    const int g    = lane >> 2;   // 0..7
    const int tg   = lane & 3;    // 0..3
    const int q0   = qt * FA_BM2;
    const int w16  = warp * 16;

    const float* Qbase = Q + (size_t)b * S_ * (NH_ * HD_)  + h * HD_;
    const float* Kbase = K + (size_t)b * S_ * (NKV_ * HD_) + kvh * HD_;
    const float* Vbase = V + (size_t)b * S_ * (NKV_ * HD_) + kvh * HD_;

    // Load + tf32-convert Q tile (128 rows x 128 dims)
#pragma unroll 4
    for (int i = 0; i < 16; ++i) {
        int lin = i * 256 + tid;
        int r   = lin >> 5;
        int d4  = (lin & 31) * 4;
        float4 v = *(const float4*)(Qbase + (size_t)(q0 + r) * (NH_ * HD_) + d4);
        v.x = f2tf32(v.x); v.y = f2tf32(v.y); v.z = f2tf32(v.z); v.w = f2tf32(v.w);
        *(float4*)(sQ + r * FB_QK_STRIDE + d4) = v;
    }

    float oacc[16][4];
#pragma unroll
    for (int n = 0; n < 16; ++n)
#pragma unroll
        for (int r = 0; r < 4; ++r) oacc[n][r] = 0.f;
    float m_i[2] = { -1e30f, -1e30f };
    float l_i[2] = { 0.f, 0.f };

    __syncthreads();

    const int njt = 2 * qt + 2;   // kv tiles of 64 covering [0, q0+128)

    for (int j = 0; j < njt; ++j) {
        const int k0 = j * 64;

        // Load + tf32-convert K and V tiles (64 rows x 128 dims each)
#pragma unroll 4
        for (int i = 0; i < 8; ++i) {
            int lin = i * 256 + tid;
            int r   = lin >> 5;
            int d4  = (lin & 31) * 4;
            float4 kv = *(const float4*)(Kbase + (size_t)(k0 + r) * (NKV_ * HD_) + d4);
            kv.x = f2tf32(kv.x); kv.y = f2tf32(kv.y); kv.z = f2tf32(kv.z); kv.w = f2tf32(kv.w);
            *(float4*)(sK + r * FB_QK_STRIDE + d4) = kv;
            float4 vv = *(const float4*)(Vbase + (size_t)(k0 + r) * (NKV_ * HD_) + d4);
            vv.x = f2tf32(vv.x); vv.y = f2tf32(vv.y); vv.z = f2tf32(vv.z); vv.w = f2tf32(vv.w);
            *(float4*)(sV + r * FB_V_STRIDE + d4) = vv;
        }
        __syncthreads();

        // ---- S = Q @ K^T (warp computes 16x64) ----
        float sacc[8][4];
#pragma unroll
        for (int n = 0; n < 8; ++n)
#pragma unroll
            for (int r = 0; r < 4; ++r) sacc[n][r] = 0.f;

#pragma unroll 2
        for (int ks = 0; ks < 16; ++ks) {
            uint32_t a[4];
            const int kc = ks * 8 + tg;
            a[0] = __float_as_uint(sQ[(w16 + g)     * FB_QK_STRIDE + kc]);
            a[1] = __float_as_uint(sQ[(w16 + g + 8) * FB_QK_STRIDE + kc]);
            a[2] = __float_as_uint(sQ[(w16 + g)     * FB_QK_STRIDE + kc + 4]);
            a[3] = __float_as_uint(sQ[(w16 + g + 8) * FB_QK_STRIDE + kc + 4]);
#pragma unroll
            for (int n = 0; n < 8; ++n) {
                uint32_t bfr[2];
                bfr[0] = __float_as_uint(sK[(n * 8 + g) * FB_QK_STRIDE + kc]);
                bfr[1] = __float_as_uint(sK[(n * 8 + g) * FB_QK_STRIDE + kc + 4]);
                mma_tf32(sacc[n], a, bfr);
            }
        }

        // ---- scale + causal mask ----
        const int r0g = q0 + w16 + g;
        const int r1g = r0g + 8;
        const bool diag = (k0 + 63 > q0 + w16);   // warp-uniform: tile may mask
#pragma unroll
        for (int n = 0; n < 8; ++n) {
            int cb = k0 + n * 8 + 2 * tg;
            float s0 = sacc[n][0] * SCALE_;
            float s1 = sacc[n][1] * SCALE_;
            float s2 = sacc[n][2] * SCALE_;
            float s3 = sacc[n][3] * SCALE_;
            if (diag) {
                if (cb     > r0g) s0 = -1e30f;
                if (cb + 1 > r0g) s1 = -1e30f;
                if (cb     > r1g) s2 = -1e30f;
                if (cb + 1 > r1g) s3 = -1e30f;
            }
            sacc[n][0] = s0; sacc[n][1] = s1; sacc[n][2] = s2; sacc[n][3] = s3;
        }

        // ---- online softmax ----
        float mx0 = -1e30f, mx1 = -1e30f;
#pragma unroll
        for (int n = 0; n < 8; ++n) {
            mx0 = fmaxf(mx0, fmaxf(sacc[n][0], sacc[n][1]));
            mx1 = fmaxf(mx1, fmaxf(sacc[n][2], sacc[n][3]));
        }
        mx0 = fmaxf(mx0, __shfl_xor_sync(0xffffffffu, mx0, 1));
        mx0 = fmaxf(mx0, __shfl_xor_sync(0xffffffffu, mx0, 2));
        mx1 = fmaxf(mx1, __shfl_xor_sync(0xffffffffu, mx1, 1));
        mx1 = fmaxf(mx1, __shfl_xor_sync(0xffffffffu, mx1, 2));

        float mn0 = fmaxf(m_i[0], mx0);
        float mn1 = fmaxf(m_i[1], mx1);
        float al0 = __expf(m_i[0] - mn0);
        float al1 = __expf(m_i[1] - mn1);
        m_i[0] = mn0; m_i[1] = mn1;

        float rs0 = 0.f, rs1 = 0.f;
#pragma unroll
        for (int n = 0; n < 8; ++n) {
            float p0 = __expf(sacc[n][0] - mn0);
            float p1 = __expf(sacc[n][1] - mn0);
            float p2 = __expf(sacc[n][2] - mn1);
            float p3 = __expf(sacc[n][3] - mn1);
            rs0 += p0 + p1;
            rs1 += p2 + p3;
            sacc[n][0] = f2tf32(p0); sacc[n][1] = f2tf32(p1);
            sacc[n][2] = f2tf32(p2); sacc[n][3] = f2tf32(p3);
        }
        rs0 += __shfl_xor_sync(0xffffffffu, rs0, 1);
        rs0 += __shfl_xor_sync(0xffffffffu, rs0, 2);
        rs1 += __shfl_xor_sync(0xffffffffu, rs1, 1);
        rs1 += __shfl_xor_sync(0xffffffffu, rs1, 2);
        l_i[0] = l_i[0] * al0 + rs0;
        l_i[1] = l_i[1] * al1 + rs1;

        // rescale O accumulator
#pragma unroll
        for (int n = 0; n < 16; ++n) {
            oacc[n][0] *= al0; oacc[n][1] *= al0;
            oacc[n][2] *= al1; oacc[n][3] *= al1;
        }

        // ---- O += P @ V ----
        const int s0l = (g << 2) + (tg >> 1);
        const int s1l = s0l + 2;
        const int sel = tg & 1;
#pragma unroll 2
        for (int ks = 0; ks < 8; ++ks) {
            uint32_t a[4];
            a[0] = __float_as_uint(quad_sel_shfl(sacc[ks][0], sacc[ks][1], s0l, sel));
            a[1] = __float_as_uint(quad_sel_shfl(sacc[ks][2], sacc[ks][3], s0l, sel));
            a[2] = __float_as_uint(quad_sel_shfl(sacc[ks][0], sacc[ks][1], s1l, sel));
            a[3] = __float_as_uint(quad_sel_shfl(sacc[ks][2], sacc[ks][3], s1l, sel));
            const int kr0 = (ks * 8 + tg) * FB_V_STRIDE;
            const int kr1 = (ks * 8 + tg + 4) * FB_V_STRIDE;
#pragma unroll 8
            for (int n = 0; n < 16; ++n) {
                uint32_t bfr[2];
                bfr[0] = __float_as_uint(sV[kr0 + n * 8 + g]);
                bfr[1] = __float_as_uint(sV[kr1 + n * 8 + g]);
                mma_tf32(oacc[n], a, bfr);
            }
        }
        __syncthreads();   // protect sK/sV before next iteration
    }

    // ---- epilogue: divide by l, write out ----
    float inv0 = 1.0f / l_i[0];
    float inv1 = 1.0f / l_i[1];
    size_t t0 = (size_t)b * S_ + q0 + w16 + g;
    size_t t1 = t0 + 8;
    float* op0 = O + t0 * (NH_ * HD_) + h * HD_;
    float* op1 = O + t1 * (NH_ * HD_) + h * HD_;
#pragma unroll
    for (int n = 0; n < 16; ++n) {
        int c = n * 8 + 2 * tg;
        float2 v0, v1;
        v0.x = oacc[n][0] * inv0; v0.y = oacc[n][1] * inv0;
        v1.x = oacc[n][2] * inv1; v1.y = oacc[n][3] * inv1;
        *(float2*)(op0 + c) = v0;
        *(float2*)(op1 + c) = v1;
    }
}

// ---------------------------------------------------------------------------
// Launch
// ---------------------------------------------------------------------------
extern "C" void kernel_launch(void* const* d_in, const int* in_sizes, int n_in,
                              void* d_out, int out_size)
{
    const float* hidden = (const float*)d_in[0];
    const int*   positions = (const int*)d_in[1];
    const float* Wq = (const float*)d_in[2];
    const float* bq = (const float*)d_in[3];
    const float* Wk = (const float*)d_in[4];
    const float* bk = (const float*)d_in[5];
    const float* Wv = (const float*)d_in[6];
    const float* bv = (const float*)d_in[7];
    const float* Wo = (const float*)d_in[8];
    float* out = (float*)d_out;

    void *pQ, *pK, *pV, *pA;
    cudaGetSymbolAddress(&pQ, g_Q);
    cudaGetSymbolAddress(&pK, g_K);
    cudaGetSymbolAddress(&pV, g_V);
    cudaGetSymbolAddress(&pA, g_ATTN);
    float* Qs = (float*)pQ;
    float* Ks = (float*)pK;
    float* Vs = (float*)pV;
    float* As = (float*)pA;

    // QKV projections (tensor cores, split-bf16)
    bf16_gemm_kernel<<<dim3((NH_ * HD_) / 128, T_ / 128), 256>>>(hidden, Wq, bq, Qs, T_, NH_ * HD_, H_);
    bf16_gemm_kernel<<<dim3((NKV_ * HD_) / 128, T_ / 128), 256>>>(hidden, Wk, bk, Ks, T_, NKV_ * HD_, H_);
    bf16_gemm_kernel<<<dim3((NKV_ * HD_) / 128, T_ / 128), 256>>>(hidden, Wv, bv, Vs, T_, NKV_ * HD_, H_);

    // RoPE on Q and K
    {
        int totq = T_ * NH_ * 64;
        rope_kernel<<<(totq + 255) / 256, 256>>>(Qs, positions, T_, NH_);
        int totk = T_ * NKV_ * 64;
        rope_kernel<<<(totk + 255) / 256, 256>>>(Ks, positions, T_, NKV_);
    }

    // Tensor-core flash attention (BM=128, 8 warps)
    size_t fa_smem = (size_t)(FA_BM2 * FB_QK_STRIDE + 64 * FB_QK_STRIDE + 64 * FB_V_STRIDE) * sizeof(float);
    cudaFuncSetAttribute(flash_attn_tc_kernel, cudaFuncAttributeMaxDynamicSharedMemorySize, (int)fa_smem);
    flash_attn_tc_kernel<<<dim3(S_ / FA_BM2, NH_, B_), 256, fa_smem>>>(Qs, Ks, Vs, As);

    // Output projection (tensor cores, split-bf16)
    bf16_gemm_kernel<<<dim3(H_ / 128, T_ / 128), 256>>>(As, Wo, nullptr, out, T_, H_, NH_ * HD_);
}

// round 11
// speedup vs baseline: 2.1735x; 1.2746x over previous
#include <cuda_runtime.h>
#include <cuda_bf16.h>
#include <cuda_fp16.h>
#include <math.h>
#include <stdint.h>

// Problem constants (fixed for this problem instance)
#define B_   2
#define S_   2048
#define H_   2048
#define NH_  16
#define NKV_ 4
#define HD_  128
#define T_   (B_ * S_)            // 4096 tokens
#define SCALE_ 0.08838834764831845f   // 128^-0.5

// ---------------------------------------------------------------------------
// Device scratch (allocation-free rule: __device__ globals)
// ---------------------------------------------------------------------------
__device__ float g_Q[T_ * NH_ * HD_];      // [4096, 2048]
__device__ float g_K[T_ * NKV_ * HD_];     // [4096, 512]
__device__ float g_V[T_ * NKV_ * HD_];     // [4096, 512]
__device__ float g_ATTN[T_ * NH_ * HD_];   // [4096, 2048]

// ---------------------------------------------------------------------------
// Numeric helpers
// ---------------------------------------------------------------------------
__device__ __forceinline__ void mma_bf16(float* d, const uint32_t* a, const uint32_t* b) {
    asm volatile(
        "mma.sync.aligned.m16n8k16.row.col.f32.bf16.bf16.f32 "
        "{%0,%1,%2,%3}, {%4,%5,%6,%7}, {%8,%9}, {%0,%1,%2,%3};"
        : "+f"(d[0]), "+f"(d[1]), "+f"(d[2]), "+f"(d[3])
        : "r"(a[0]), "r"(a[1]), "r"(a[2]), "r"(a[3]), "r"(b[0]), "r"(b[1]));
}
__device__ __forceinline__ void mma_f16(float* d, const uint32_t* a, const uint32_t* b) {
    asm volatile(
        "mma.sync.aligned.m16n8k16.row.col.f32.f16.f16.f32 "
        "{%0,%1,%2,%3}, {%4,%5,%6,%7}, {%8,%9}, {%0,%1,%2,%3};"
        : "+f"(d[0]), "+f"(d[1]), "+f"(d[2]), "+f"(d[3])
        : "r"(a[0]), "r"(a[1]), "r"(a[2]), "r"(a[3]), "r"(b[0]), "r"(b[1]));
}
__device__ __forceinline__ void split_bf16(float x, float& h, float& l) {
    __nv_bfloat16 hb = __float2bfloat16_rn(x);
    h = __bfloat162float(hb);
    l = x - h;
}
__device__ __forceinline__ uint32_t bf16x2(float x, float y) {
    __nv_bfloat162 t = __floats2bfloat162_rn(x, y);   // x -> low half (even k)
    return *reinterpret_cast<uint32_t*>(&t);
}
__device__ __forceinline__ uint32_t h2pack(float x, float y) {
    __half2 t = __floats2half2_rn(x, y);              // x -> low half (even k)
    return *reinterpret_cast<uint32_t*>(&t);
}

// ---------------------------------------------------------------------------
// Split-BF16 tensor-core GEMM (hi/lo, 3 MMAs m16n8k16) — ~fp32-accurate.
// (unchanged from R8/R9 passing version)
// ---------------------------------------------------------------------------
#define GB_STRIDE 12

__global__ __launch_bounds__(256) void bf16_gemm_kernel(
    const float* __restrict__ A, const float* __restrict__ Bm,
    const float* __restrict__ bias, float* __restrict__ C,
    int M, int N, int K)
{
    __shared__ uint32_t Ah[128 * GB_STRIDE];
    __shared__ uint32_t Al[128 * GB_STRIDE];
    __shared__ uint32_t Bh[128 * GB_STRIDE];
    __shared__ uint32_t Bl[128 * GB_STRIDE];

    const int tid  = threadIdx.x;
    const int warp = tid >> 5;
    const int lane = tid & 31;
    const int g    = lane >> 2;
    const int tg   = lane & 3;
    const int wm   = warp >> 2;
    const int wn   = warp & 3;

    const int bm = blockIdx.y;
    const int bn = blockIdx.x;

    const float* Ab = A + (size_t)(bm * 128) * K;
    const float* Bb = Bm + bn * 128;

    float acc[4][4][4];
#pragma unroll
    for (int mi = 0; mi < 4; ++mi)
#pragma unroll
        for (int ni = 0; ni < 4; ++ni)
#pragma unroll
            for (int r = 0; r < 4; ++r) acc[mi][ni][r] = 0.f;

    float2 aReg[4];
    float  bReg[4][2];

    auto load_tile = [&](int k0) {
#pragma unroll
        for (int i = 0; i < 4; ++i) {
            int p  = i * 256 + tid;
            int ar = p >> 3, ak = p & 7;
            aReg[i] = *(const float2*)(Ab + (size_t)ar * K + k0 + 2 * ak);
            int bk = (p >> 7) & 7, bnn = p & 127;
            bReg[i][0] = Bb[(size_t)(k0 + 2 * bk)     * N + bnn];
            bReg[i][1] = Bb[(size_t)(k0 + 2 * bk + 1) * N + bnn];
        }
    };
    auto store_tile = [&]() {
#pragma unroll
        for (int i = 0; i < 4; ++i) {
            int p  = i * 256 + tid;
            int ar = p >> 3, ak = p & 7;
            float hx, lx, hy, ly;
            split_bf16(aReg[i].x, hx, lx);
            split_bf16(aReg[i].y, hy, ly);
            Ah[ar * GB_STRIDE + ak] = bf16x2(hx, hy);
            Al[ar * GB_STRIDE + ak] = bf16x2(lx, ly);
            int bk = (p >> 7) & 7, bnn = p & 127;
            float h0, l0, h1, l1;
            split_bf16(bReg[i][0], h0, l0);
            split_bf16(bReg[i][1], h1, l1);
            Bh[bnn * GB_STRIDE + bk] = bf16x2(h0, h1);
            Bl[bnn * GB_STRIDE + bk] = bf16x2(l0, l1);
        }
    };

    const int ntiles = K / 16;

    load_tile(0);
    store_tile();
    __syncthreads();

    for (int t = 0; t < ntiles; ++t) {
        if (t + 1 < ntiles) load_tile((t + 1) * 16);

        uint32_t ah[4][4], al[4][4];
        uint32_t bh[4][2], bl[4][2];
#pragma unroll
        for (int mi = 0; mi < 4; ++mi) {
            int r0 = (wm * 64 + mi * 16 + g) * GB_STRIDE;
            ah[mi][0] = Ah[r0 + tg];
            ah[mi][1] = Ah[r0 + 8 * GB_STRIDE + tg];
            ah[mi][2] = Ah[r0 + tg + 4];
            ah[mi][3] = Ah[r0 + 8 * GB_STRIDE + tg + 4];
            al[mi][0] = Al[r0 + tg];
            al[mi][1] = Al[r0 + 8 * GB_STRIDE + tg];
            al[mi][2] = Al[r0 + tg + 4];
            al[mi][3] = Al[r0 + 8 * GB_STRIDE + tg + 4];
        }
#pragma unroll
        for (int ni = 0; ni < 4; ++ni) {
            int n0 = (wn * 32 + ni * 8 + g) * GB_STRIDE;
            bh[ni][0] = Bh[n0 + tg];
            bh[ni][1] = Bh[n0 + tg + 4];
            bl[ni][0] = Bl[n0 + tg];
            bl[ni][1] = Bl[n0 + tg + 4];
        }
#pragma unroll
        for (int mi = 0; mi < 4; ++mi)
#pragma unroll
            for (int ni = 0; ni < 4; ++ni) {
                mma_bf16(acc[mi][ni], ah[mi], bh[ni]);
                mma_bf16(acc[mi][ni], al[mi], bh[ni]);
                mma_bf16(acc[mi][ni], ah[mi], bl[ni]);
            }
        __syncthreads();
        if (t + 1 < ntiles) {
            store_tile();
            __syncthreads();
        }
    }

#pragma unroll
    for (int mi = 0; mi < 4; ++mi) {
        int r0 = bm * 128 + wm * 64 + mi * 16 + g;
#pragma unroll
        for (int ni = 0; ni < 4; ++ni) {
            int c = bn * 128 + wn * 32 + ni * 8 + 2 * tg;
            float b0 = 0.f, b1 = 0.f;
            if (bias) { b0 = bias[c]; b1 = bias[c + 1]; }
            float2 o0, o1;
            o0.x = acc[mi][ni][0] + b0; o0.y = acc[mi][ni][1] + b1;
            o1.x = acc[mi][ni][2] + b0; o1.y = acc[mi][ni][3] + b1;
            *(float2*)(C + (size_t)r0 * N + c)       = o0;
            *(float2*)(C + (size_t)(r0 + 8) * N + c) = o1;
        }
    }
}

// ---------------------------------------------------------------------------
// Neox RoPE applied in-place to x[T, nheads*128].
// ---------------------------------------------------------------------------
__global__ void rope_kernel(float* __restrict__ x, const int* __restrict__ positions,
                            int Ttot, int nheads)
{
    int idx = blockIdx.x * blockDim.x + threadIdx.x;
    int total = Ttot * nheads * (HD_ / 2);
    if (idx >= total) return;
    int i = idx & 63;
    int h = (idx >> 6) % nheads;
    int t = idx / (64 * nheads);

    int pos = positions[t % S_];
    float inv_freq = powf(10000.0f, -((float)(2 * i)) / (float)HD_);
    float freq = (float)pos * inv_freq;
    float s, c;
    sincosf(freq, &s, &c);

    size_t base = (size_t)t * (nheads * HD_) + h * HD_;
    float x1 = x[base + i];
    float x2 = x[base + 64 + i];
    x[base + i]      = x1 * c - x2 * s;
    x[base + 64 + i] = x2 * c + x1 * s;
}

// ---------------------------------------------------------------------------
// FP16 tensor-core flash attention (m16n8k16, causal, GQA rep=4).
// Block: 256 threads (8 warps); BM=128 query rows (16 per warp), BN=64.
// SMEM (uint32 words): sQ[128][68] half2 k-pairs, sK[64][68] half2 k-pairs,
//                      sVt[128 dims][36] half2 kv-pairs (transposed V).
// P acc -> A fragment is a local half2 pack (no shuffles with k16).
// ---------------------------------------------------------------------------
#define QKW 68     // words per Q/K row (64 data + 4 pad) -> banks 4g+tg, conflict-free
#define VTW 36     // words per V-dim row (32 data + 4 pad) -> banks 4g+tg, conflict-free
#define FA_BM2 128

__global__ __launch_bounds__(256) void flash_attn_fp16_kernel(
    const float* __restrict__ Q, const float* __restrict__ K,
    const float* __restrict__ V, float* __restrict__ O)
{
    extern __shared__ uint32_t smu[];
    uint32_t* sQ  = smu;                        // 128*68
    uint32_t* sK  = sQ + FA_BM2 * QKW;          // 64*68
    uint32_t* sVt = sK + 64 * QKW;              // 128*36
    __half*   sVh = (__half*)sVt;               // halves, row stride 72

    const int qt = blockIdx.x;
    const int h  = blockIdx.y;
    const int b  = blockIdx.z;
    const int kvh = h >> 2;

    const int tid  = threadIdx.x;
    const int warp = tid >> 5;
    const int lane = tid & 31;
    const int g    = lane >> 2;   // 0..7
    const int tg   = lane & 3;    // 0..3
    const int q0   = qt * FA_BM2;
    const int w16  = warp * 16;

    const float* Qbase = Q + (size_t)b * S_ * (NH_ * HD_)  + h * HD_;
    const float* Kbase = K + (size_t)b * S_ * (NKV_ * HD_) + kvh * HD_;
    const float* Vbase = V + (size_t)b * S_ * (NKV_ * HD_) + kvh * HD_;

    // Load + fp16-convert Q tile (128 rows x 128 dims)
#pragma unroll 4
    for (int i = 0; i < 16; ++i) {
        int lin = i * 256 + tid;
        int r   = lin >> 5;
        int d4  = (lin & 31) * 4;
        float4 v = *(const float4*)(Qbase + (size_t)(q0 + r) * (NH_ * HD_) + d4);
        sQ[r * QKW + (d4 >> 1)]     = h2pack(v.x, v.y);
        sQ[r * QKW + (d4 >> 1) + 1] = h2pack(v.z, v.w);
    }

    float oacc[16][4];
#pragma unroll
    for (int n = 0; n < 16; ++n)
#pragma unroll
        for (int r = 0; r < 4; ++r) oacc[n][r] = 0.f;
    float m_i[2] = { -1e30f, -1e30f };
    float l_i[2] = { 0.f, 0.f };

    __syncthreads();

    const int njt = 2 * qt + 2;   // kv tiles of 64 covering [0, q0+128)

    for (int j = 0; j < njt; ++j) {
        const int k0 = j * 64;

        // K tile: 64 rows x 128 dims, half2 along dims
#pragma unroll 4
        for (int i = 0; i < 8; ++i) {
            int lin = i * 256 + tid;
            int r   = lin >> 5;
            int d4  = (lin & 31) * 4;
            float4 kv = *(const float4*)(Kbase + (size_t)(k0 + r) * (NKV_ * HD_) + d4);
            sK[r * QKW + (d4 >> 1)]     = h2pack(kv.x, kv.y);
            sK[r * QKW + (d4 >> 1) + 1] = h2pack(kv.z, kv.w);
        }
        // V tile transposed: scalar loads (coalesced), half stores
#pragma unroll 4
        for (int i = 0; i < 32; ++i) {
            int lin = i * 256 + tid;
            int dim = lin & 127;
            int r   = lin >> 7;
            float v = Vbase[(size_t)(k0 + r) * (NKV_ * HD_) + dim];
            sVh[dim * (2 * VTW) + r] = __float2half_rn(v);
        }
        __syncthreads();

        // Per-warp skip of fully-masked tiles (warp-uniform)
        if (k0 <= q0 + w16 + 15) {
            // ---- S = Q @ K^T (fp16 k16; warp computes 16x64) ----
            float sacc[8][4];
#pragma unroll
            for (int n = 0; n < 8; ++n)
#pragma unroll
                for (int r = 0; r < 4; ++r) sacc[n][r] = 0.f;

#pragma unroll 2
            for (int ks = 0; ks < 8; ++ks) {
                uint32_t a[4];
                const int kc = ks * 8 + tg;
                a[0] = sQ[(w16 + g)     * QKW + kc];
                a[1] = sQ[(w16 + g + 8) * QKW + kc];
                a[2] = sQ[(w16 + g)     * QKW + kc + 4];
                a[3] = sQ[(w16 + g + 8) * QKW + kc + 4];
#pragma unroll
                for (int n = 0; n < 8; ++n) {
                    uint32_t bfr[2];
                    bfr[0] = sK[(n * 8 + g) * QKW + kc];
                    bfr[1] = sK[(n * 8 + g) * QKW + kc + 4];
                    mma_f16(sacc[n], a, bfr);
                }
            }

            // ---- scale + causal mask ----
            const int r0g = q0 + w16 + g;
            const int r1g = r0g + 8;
            const bool diag = (k0 + 63 > q0 + w16);
#pragma unroll
            for (int n = 0; n < 8; ++n) {
                int cb = k0 + n * 8 + 2 * tg;
                float s0 = sacc[n][0] * SCALE_;
                float s1 = sacc[n][1] * SCALE_;
                float s2 = sacc[n][2] * SCALE_;
                float s3 = sacc[n][3] * SCALE_;
                if (diag) {
                    if (cb     > r0g) s0 = -1e30f;
                    if (cb + 1 > r0g) s1 = -1e30f;
                    if (cb     > r1g) s2 = -1e30f;
                    if (cb + 1 > r1g) s3 = -1e30f;
                }
                sacc[n][0] = s0; sacc[n][1] = s1; sacc[n][2] = s2; sacc[n][3] = s3;
            }

            // ---- online softmax ----
            float mx0 = -1e30f, mx1 = -1e30f;
#pragma unroll
            for (int n = 0; n < 8; ++n) {
                mx0 = fmaxf(mx0, fmaxf(sacc[n][0], sacc[n][1]));
                mx1 = fmaxf(mx1, fmaxf(sacc[n][2], sacc[n][3]));
            }
            mx0 = fmaxf(mx0, __shfl_xor_sync(0xffffffffu, mx0, 1));
            mx0 = fmaxf(mx0, __shfl_xor_sync(0xffffffffu, mx0, 2));
            mx1 = fmaxf(mx1, __shfl_xor_sync(0xffffffffu, mx1, 1));
            mx1 = fmaxf(mx1, __shfl_xor_sync(0xffffffffu, mx1, 2));

            float mn0 = fmaxf(m_i[0], mx0);
            float mn1 = fmaxf(m_i[1], mx1);
            float al0 = __expf(m_i[0] - mn0);
            float al1 = __expf(m_i[1] - mn1);
            m_i[0] = mn0; m_i[1] = mn1;

            // exp + pack P into fp16 A-fragment words (no shuffles needed at k16)
            uint32_t pk[8][2];
            float rs0 = 0.f, rs1 = 0.f;
#pragma unroll
            for (int n = 0; n < 8; ++n) {
                float p0 = __expf(sacc[n][0] - mn0);
                float p1 = __expf(sacc[n][1] - mn0);
                float p2 = __expf(sacc[n][2] - mn1);
                float p3 = __expf(sacc[n][3] - mn1);
                rs0 += p0 + p1;
                rs1 += p2 + p3;
                pk[n][0] = h2pack(p0, p1);
                pk[n][1] = h2pack(p2, p3);
            }
            rs0 += __shfl_xor_sync(0xffffffffu, rs0, 1);
            rs0 += __shfl_xor_sync(0xffffffffu, rs0, 2);
            rs1 += __shfl_xor_sync(0xffffffffu, rs1, 1);
            rs1 += __shfl_xor_sync(0xffffffffu, rs1, 2);
            l_i[0] = l_i[0] * al0 + rs0;
            l_i[1] = l_i[1] * al1 + rs1;

            // rescale O accumulator
#pragma unroll
            for (int n = 0; n < 16; ++n) {
                oacc[n][0] *= al0; oacc[n][1] *= al0;
                oacc[n][2] *= al1; oacc[n][3] *= al1;
            }

            // ---- O += P @ V (fp16 k16, V transposed in smem) ----
#pragma unroll
            for (int ks = 0; ks < 4; ++ks) {
                uint32_t a[4];
                a[0] = pk[2 * ks][0];
                a[1] = pk[2 * ks][1];
                a[2] = pk[2 * ks + 1][0];
                a[3] = pk[2 * ks + 1][1];
                const int kc = ks * 8 + tg;
#pragma unroll 8
                for (int n = 0; n < 16; ++n) {
                    uint32_t bfr[2];
                    bfr[0] = sVt[(n * 8 + g) * VTW + kc];
                    bfr[1] = sVt[(n * 8 + g) * VTW + kc + 4];
                    mma_f16(oacc[n], a, bfr);
                }
            }
        }
        __syncthreads();   // protect sK/sVt before next iteration
    }

    // ---- epilogue: divide by l, write out ----
    float inv0 = 1.0f / l_i[0];
    float inv1 = 1.0f / l_i[1];
    size_t t0 = (size_t)b * S_ + q0 + w16 + g;
    size_t t1 = t0 + 8;
    float* op0 = O + t0 * (NH_ * HD_) + h * HD_;
    float* op1 = O + t1 * (NH_ * HD_) + h * HD_;
#pragma unroll
    for (int n = 0; n < 16; ++n) {
        int c = n * 8 + 2 * tg;
        float2 v0, v1;
        v0.x = oacc[n][0] * inv0; v0.y = oacc[n][1] * inv0;
        v1.x = oacc[n][2] * inv1; v1.y = oacc[n][3] * inv1;
        *(float2*)(op0 + c) = v0;
        *(float2*)(op1 + c) = v1;
    }
}

// ---------------------------------------------------------------------------
// Launch
// ---------------------------------------------------------------------------
extern "C" void kernel_launch(void* const* d_in, const int* in_sizes, int n_in,
                              void* d_out, int out_size)
{
    const float* hidden = (const float*)d_in[0];
    const int*   positions = (const int*)d_in[1];
    const float* Wq = (const float*)d_in[2];
    const float* bq = (const float*)d_in[3];
    const float* Wk = (const float*)d_in[4];
    const float* bk = (const float*)d_in[5];
    const float* Wv = (const float*)d_in[6];
    const float* bv = (const float*)d_in[7];
    const float* Wo = (const float*)d_in[8];
    float* out = (float*)d_out;

    void *pQ, *pK, *pV, *pA;
    cudaGetSymbolAddress(&pQ, g_Q);
    cudaGetSymbolAddress(&pK, g_K);
    cudaGetSymbolAddress(&pV, g_V);
    cudaGetSymbolAddress(&pA, g_ATTN);
    float* Qs = (float*)pQ;
    float* Ks = (float*)pK;
    float* Vs = (float*)pV;
    float* As = (float*)pA;

    // QKV projections (tensor cores, split-bf16)
    bf16_gemm_kernel<<<dim3((NH_ * HD_) / 128, T_ / 128), 256>>>(hidden, Wq, bq, Qs, T_, NH_ * HD_, H_);
    bf16_gemm_kernel<<<dim3((NKV_ * HD_) / 128, T_ / 128), 256>>>(hidden, Wk, bk, Ks, T_, NKV_ * HD_, H_);
    bf16_gemm_kernel<<<dim3((NKV_ * HD_) / 128, T_ / 128), 256>>>(hidden, Wv, bv, Vs, T_, NKV_ * HD_, H_);

    // RoPE on Q and K
    {
        int totq = T_ * NH_ * 64;
        rope_kernel<<<(totq + 255) / 256, 256>>>(Qs, positions, T_, NH_);
        int totk = T_ * NKV_ * 64;
        rope_kernel<<<(totk + 255) / 256, 256>>>(Ks, positions, T_, NKV_);
    }

    // FP16 tensor-core flash attention (BM=128, 8 warps)
    size_t fa_smem = (size_t)(FA_BM2 * QKW + 64 * QKW + FA_BM2 * VTW) * sizeof(uint32_t);
    cudaFuncSetAttribute(flash_attn_fp16_kernel, cudaFuncAttributeMaxDynamicSharedMemorySize, (int)fa_smem);
    flash_attn_fp16_kernel<<<dim3(S_ / FA_BM2, NH_, B_), 256, fa_smem>>>(Qs, Ks, Vs, As);

    // Output projection (tensor cores, split-bf16)
    bf16_gemm_kernel<<<dim3(H_ / 128, T_ / 128), 256>>>(As, Wo, nullptr, out, T_, H_, NH_ * HD_);
}

// round 12
// speedup vs baseline: 2.6046x; 1.1983x over previous
#include <cuda_runtime.h>
#include <cuda_bf16.h>
#include <cuda_fp16.h>
#include <math.h>
#include <stdint.h>

// Problem constants (fixed for this problem instance)
#define B_   2
#define S_   2048
#define H_   2048
#define NH_  16
#define NKV_ 4
#define HD_  128
#define T_   (B_ * S_)            // 4096 tokens
#define SCALE_ 0.08838834764831845f   // 128^-0.5

// ---------------------------------------------------------------------------
// Device scratch (allocation-free rule: __device__ globals)
// ---------------------------------------------------------------------------
__device__ float g_Q[T_ * NH_ * HD_];      // [4096, 2048]
__device__ float g_K[T_ * NKV_ * HD_];     // [4096, 512]
__device__ float g_V[T_ * NKV_ * HD_];     // [4096, 512]
__device__ float g_ATTN[T_ * NH_ * HD_];   // [4096, 2048]

// ---------------------------------------------------------------------------
// Numeric helpers
// ---------------------------------------------------------------------------
__device__ __forceinline__ void mma_f16(float* d, const uint32_t* a, const uint32_t* b) {
    asm volatile(
        "mma.sync.aligned.m16n8k16.row.col.f32.f16.f16.f32 "
        "{%0,%1,%2,%3}, {%4,%5,%6,%7}, {%8,%9}, {%0,%1,%2,%3};"
        : "+f"(d[0]), "+f"(d[1]), "+f"(d[2]), "+f"(d[3])
        : "r"(a[0]), "r"(a[1]), "r"(a[2]), "r"(a[3]), "r"(b[0]), "r"(b[1]));
}
__device__ __forceinline__ void split_f16(float x, float& h, float& l) {
    __half hb = __float2half_rn(x);
    h = __half2float(hb);
    l = x - h;
}
__device__ __forceinline__ uint32_t h2pack(float x, float y) {
    __half2 t = __floats2half2_rn(x, y);              // x -> low half (even k)
    return *reinterpret_cast<uint32_t*>(&t);
}

// ---------------------------------------------------------------------------
// Split-FP16 tensor-core GEMM.
// TWO=true : C = Ah*Bh + Al*Bh  (A split hi/lo, B hi only; ~1.4e-4 rel err)
// TWO=false: C = Ah*Bh          (plain fp16; ~2e-4 rel err)
// C[M,N] = A[M,K] @ B[K,N] (+bias); row-major. Tile 128x128x16, 256 thr.
// SMEM rows padded to 12 words: (12g+tg) mod 32 conflict-free.
// ---------------------------------------------------------------------------
#define GB_STRIDE 12

template<bool TWO>
__global__ __launch_bounds__(256) void f16_gemm_kernel(
    const float* __restrict__ A, const float* __restrict__ Bm,
    const float* __restrict__ bias, float* __restrict__ C,
    int M, int N, int K)
{
    __shared__ uint32_t Ah[128 * GB_STRIDE];
    __shared__ uint32_t Al[TWO ? 128 * GB_STRIDE : 32];
    __shared__ uint32_t Bh[128 * GB_STRIDE];

    const int tid  = threadIdx.x;
    const int warp = tid >> 5;
    const int lane = tid & 31;
    const int g    = lane >> 2;
    const int tg   = lane & 3;
    const int wm   = warp >> 2;
    const int wn   = warp & 3;

    const int bm = blockIdx.y;
    const int bn = blockIdx.x;

    const float* Ab = A + (size_t)(bm * 128) * K;
    const float* Bb = Bm + bn * 128;

    float acc[4][4][4];
#pragma unroll
    for (int mi = 0; mi < 4; ++mi)
#pragma unroll
        for (int ni = 0; ni < 4; ++ni)
#pragma unroll
            for (int r = 0; r < 4; ++r) acc[mi][ni][r] = 0.f;

    float2 aReg[4];
    float  bReg[4][2];

    auto load_tile = [&](int k0) {
#pragma unroll
        for (int i = 0; i < 4; ++i) {
            int p  = i * 256 + tid;
            int ar = p >> 3, ak = p & 7;
            aReg[i] = *(const float2*)(Ab + (size_t)ar * K + k0 + 2 * ak);
            int bk = (p >> 7) & 7, bnn = p & 127;
            bReg[i][0] = Bb[(size_t)(k0 + 2 * bk)     * N + bnn];
            bReg[i][1] = Bb[(size_t)(k0 + 2 * bk + 1) * N + bnn];
        }
    };
    auto store_tile = [&]() {
#pragma unroll
        for (int i = 0; i < 4; ++i) {
            int p  = i * 256 + tid;
            int ar = p >> 3, ak = p & 7;
            float hx, lx, hy, ly;
            split_f16(aReg[i].x, hx, lx);
            split_f16(aReg[i].y, hy, ly);
            Ah[ar * GB_STRIDE + ak] = h2pack(hx, hy);
            if (TWO) Al[ar * GB_STRIDE + ak] = h2pack(lx, ly);
            int bk = (p >> 7) & 7, bnn = p & 127;
            Bh[bnn * GB_STRIDE + bk] = h2pack(bReg[i][0], bReg[i][1]);
        }
    };

    const int ntiles = K / 16;

    load_tile(0);
    store_tile();
    __syncthreads();

    for (int t = 0; t < ntiles; ++t) {
        if (t + 1 < ntiles) load_tile((t + 1) * 16);

        uint32_t ah[4][4], al[4][4];
        uint32_t bh[4][2];
#pragma unroll
        for (int mi = 0; mi < 4; ++mi) {
            int r0 = (wm * 64 + mi * 16 + g) * GB_STRIDE;
            ah[mi][0] = Ah[r0 + tg];
            ah[mi][1] = Ah[r0 + 8 * GB_STRIDE + tg];
            ah[mi][2] = Ah[r0 + tg + 4];
            ah[mi][3] = Ah[r0 + 8 * GB_STRIDE + tg + 4];
            if (TWO) {
                al[mi][0] = Al[r0 + tg];
                al[mi][1] = Al[r0 + 8 * GB_STRIDE + tg];
                al[mi][2] = Al[r0 + tg + 4];
                al[mi][3] = Al[r0 + 8 * GB_STRIDE + tg + 4];
            }
        }
#pragma unroll
        for (int ni = 0; ni < 4; ++ni) {
            int n0 = (wn * 32 + ni * 8 + g) * GB_STRIDE;
            bh[ni][0] = Bh[n0 + tg];
            bh[ni][1] = Bh[n0 + tg + 4];
        }
#pragma unroll
        for (int mi = 0; mi < 4; ++mi)
#pragma unroll
            for (int ni = 0; ni < 4; ++ni) {
                mma_f16(acc[mi][ni], ah[mi], bh[ni]);
                if (TWO) mma_f16(acc[mi][ni], al[mi], bh[ni]);
            }
        __syncthreads();
        if (t + 1 < ntiles) {
            store_tile();
            __syncthreads();
        }
    }

#pragma unroll
    for (int mi = 0; mi < 4; ++mi) {
        int r0 = bm * 128 + wm * 64 + mi * 16 + g;
#pragma unroll
        for (int ni = 0; ni < 4; ++ni) {
            int c = bn * 128 + wn * 32 + ni * 8 + 2 * tg;
            float b0 = 0.f, b1 = 0.f;
            if (bias) { b0 = bias[c]; b1 = bias[c + 1]; }
            float2 o0, o1;
            o0.x = acc[mi][ni][0] + b0; o0.y = acc[mi][ni][1] + b1;
            o1.x = acc[mi][ni][2] + b0; o1.y = acc[mi][ni][3] + b1;
            *(float2*)(C + (size_t)r0 * N + c)       = o0;
            *(float2*)(C + (size_t)(r0 + 8) * N + c) = o1;
        }
    }
}

// ---------------------------------------------------------------------------
// Neox RoPE applied in-place to x[T, nheads*128].
// ---------------------------------------------------------------------------
__global__ void rope_kernel(float* __restrict__ x, const int* __restrict__ positions,
                            int Ttot, int nheads)
{
    int idx = blockIdx.x * blockDim.x + threadIdx.x;
    int total = Ttot * nheads * (HD_ / 2);
    if (idx >= total) return;
    int i = idx & 63;
    int h = (idx >> 6) % nheads;
    int t = idx / (64 * nheads);

    int pos = positions[t % S_];
    float inv_freq = powf(10000.0f, -((float)(2 * i)) / (float)HD_);
    float freq = (float)pos * inv_freq;
    float s, c;
    sincosf(freq, &s, &c);

    size_t base = (size_t)t * (nheads * HD_) + h * HD_;
    float x1 = x[base + i];
    float x2 = x[base + 64 + i];
    x[base + i]      = x1 * c - x2 * s;
    x[base + 64 + i] = x2 * c + x1 * s;
}

// ---------------------------------------------------------------------------
// FP16 tensor-core flash attention (m16n8k16, causal, GQA rep=4).
// Unchanged from R11 passing version.
// ---------------------------------------------------------------------------
#define QKW 68
#define VTW 36
#define FA_BM2 128

__global__ __launch_bounds__(256) void flash_attn_fp16_kernel(
    const float* __restrict__ Q, const float* __restrict__ K,
    const float* __restrict__ V, float* __restrict__ O)
{
    extern __shared__ uint32_t smu[];
    uint32_t* sQ  = smu;                        // 128*68
    uint32_t* sK  = sQ + FA_BM2 * QKW;          // 64*68
    uint32_t* sVt = sK + 64 * QKW;              // 128*36
    __half*   sVh = (__half*)sVt;               // halves, row stride 72

    const int qt = blockIdx.x;
    const int h  = blockIdx.y;
    const int b  = blockIdx.z;
    const int kvh = h >> 2;

    const int tid  = threadIdx.x;
    const int warp = tid >> 5;
    const int lane = tid & 31;
    const int g    = lane >> 2;   // 0..7
    const int tg   = lane & 3;    // 0..3
    const int q0   = qt * FA_BM2;
    const int w16  = warp * 16;

    const float* Qbase = Q + (size_t)b * S_ * (NH_ * HD_)  + h * HD_;
    const float* Kbase = K + (size_t)b * S_ * (NKV_ * HD_) + kvh * HD_;
    const float* Vbase = V + (size_t)b * S_ * (NKV_ * HD_) + kvh * HD_;

#pragma unroll 4
    for (int i = 0; i < 16; ++i) {
        int lin = i * 256 + tid;
        int r   = lin >> 5;
        int d4  = (lin & 31) * 4;
        float4 v = *(const float4*)(Qbase + (size_t)(q0 + r) * (NH_ * HD_) + d4);
        sQ[r * QKW + (d4 >> 1)]     = h2pack(v.x, v.y);
        sQ[r * QKW + (d4 >> 1) + 1] = h2pack(v.z, v.w);
    }

    float oacc[16][4];
#pragma unroll
    for (int n = 0; n < 16; ++n)
#pragma unroll
        for (int r = 0; r < 4; ++r) oacc[n][r] = 0.f;
    float m_i[2] = { -1e30f, -1e30f };
    float l_i[2] = { 0.f, 0.f };

    __syncthreads();

    const int njt = 2 * qt + 2;

    for (int j = 0; j < njt; ++j) {
        const int k0 = j * 64;

#pragma unroll 4
        for (int i = 0; i < 8; ++i) {
            int lin = i * 256 + tid;
            int r   = lin >> 5;
            int d4  = (lin & 31) * 4;
            float4 kv = *(const float4*)(Kbase + (size_t)(k0 + r) * (NKV_ * HD_) + d4);
            sK[r * QKW + (d4 >> 1)]     = h2pack(kv.x, kv.y);
            sK[r * QKW + (d4 >> 1) + 1] = h2pack(kv.z, kv.w);
        }
#pragma unroll 4
        for (int i = 0; i < 32; ++i) {
            int lin = i * 256 + tid;
            int dim = lin & 127;
            int r   = lin >> 7;
            float v = Vbase[(size_t)(k0 + r) * (NKV_ * HD_) + dim];
            sVh[dim * (2 * VTW) + r] = __float2half_rn(v);
        }
        __syncthreads();

        if (k0 <= q0 + w16 + 15) {
            float sacc[8][4];
#pragma unroll
            for (int n = 0; n < 8; ++n)
#pragma unroll
                for (int r = 0; r < 4; ++r) sacc[n][r] = 0.f;

#pragma unroll 2
            for (int ks = 0; ks < 8; ++ks) {
                uint32_t a[4];
                const int kc = ks * 8 + tg;
                a[0] = sQ[(w16 + g)     * QKW + kc];
                a[1] = sQ[(w16 + g + 8) * QKW + kc];
                a[2] = sQ[(w16 + g)     * QKW + kc + 4];
                a[3] = sQ[(w16 + g + 8) * QKW + kc + 4];
#pragma unroll
                for (int n = 0; n < 8; ++n) {
                    uint32_t bfr[2];
                    bfr[0] = sK[(n * 8 + g) * QKW + kc];
                    bfr[1] = sK[(n * 8 + g) * QKW + kc + 4];
                    mma_f16(sacc[n], a, bfr);
                }
            }

            const int r0g = q0 + w16 + g;
            const int r1g = r0g + 8;
            const bool diag = (k0 + 63 > q0 + w16);
#pragma unroll
            for (int n = 0; n < 8; ++n) {
                int cb = k0 + n * 8 + 2 * tg;
                float s0 = sacc[n][0] * SCALE_;
                float s1 = sacc[n][1] * SCALE_;
                float s2 = sacc[n][2] * SCALE_;
                float s3 = sacc[n][3] * SCALE_;
                if (diag) {
                    if (cb     > r0g) s0 = -1e30f;
                    if (cb + 1 > r0g) s1 = -1e30f;
                    if (cb     > r1g) s2 = -1e30f;
                    if (cb + 1 > r1g) s3 = -1e30f;
                }
                sacc[n][0] = s0; sacc[n][1] = s1; sacc[n][2] = s2; sacc[n][3] = s3;
            }

            float mx0 = -1e30f, mx1 = -1e30f;
#pragma unroll
            for (int n = 0; n < 8; ++n) {
                mx0 = fmaxf(mx0, fmaxf(sacc[n][0], sacc[n][1]));
                mx1 = fmaxf(mx1, fmaxf(sacc[n][2], sacc[n][3]));
            }
            mx0 = fmaxf(mx0, __shfl_xor_sync(0xffffffffu, mx0, 1));
            mx0 = fmaxf(mx0, __shfl_xor_sync(0xffffffffu, mx0, 2));
            mx1 = fmaxf(mx1, __shfl_xor_sync(0xffffffffu, mx1, 1));
            mx1 = fmaxf(mx1, __shfl_xor_sync(0xffffffffu, mx1, 2));

            float mn0 = fmaxf(m_i[0], mx0);
            float mn1 = fmaxf(m_i[1], mx1);
            float al0 = __expf(m_i[0] - mn0);
            float al1 = __expf(m_i[1] - mn1);
            m_i[0] = mn0; m_i[1] = mn1;

            uint32_t pk[8][2];
            float rs0 = 0.f, rs1 = 0.f;
#pragma unroll
            for (int n = 0; n < 8; ++n) {
                float p0 = __expf(sacc[n][0] - mn0);
                float p1 = __expf(sacc[n][1] - mn0);
                float p2 = __expf(sacc[n][2] - mn1);
                float p3 = __expf(sacc[n][3] - mn1);
                rs0 += p0 + p1;
                rs1 += p2 + p3;
                pk[n][0] = h2pack(p0, p1);
                pk[n][1] = h2pack(p2, p3);
            }
            rs0 += __shfl_xor_sync(0xffffffffu, rs0, 1);
            rs0 += __shfl_xor_sync(0xffffffffu, rs0, 2);
            rs1 += __shfl_xor_sync(0xffffffffu, rs1, 1);
            rs1 += __shfl_xor_sync(0xffffffffu, rs1, 2);
            l_i[0] = l_i[0] * al0 + rs0;
            l_i[1] = l_i[1] * al1 + rs1;

#pragma unroll
            for (int n = 0; n < 16; ++n) {
                oacc[n][0] *= al0; oacc[n][1] *= al0;
                oacc[n][2] *= al1; oacc[n][3] *= al1;
            }

#pragma unroll
            for (int ks = 0; ks < 4; ++ks) {
                uint32_t a[4];
                a[0] = pk[2 * ks][0];
                a[1] = pk[2 * ks][1];
                a[2] = pk[2 * ks + 1][0];
                a[3] = pk[2 * ks + 1][1];
                const int kc = ks * 8 + tg;
#pragma unroll 8
                for (int n = 0; n < 16; ++n) {
                    uint32_t bfr[2];
                    bfr[0] = sVt[(n * 8 + g) * VTW + kc];
                    bfr[1] = sVt[(n * 8 + g) * VTW + kc + 4];
                    mma_f16(oacc[n], a, bfr);
                }
            }
        }
        __syncthreads();
    }

    float inv0 = 1.0f / l_i[0];
    float inv1 = 1.0f / l_i[1];
    size_t t0 = (size_t)b * S_ + q0 + w16 + g;
    size_t t1 = t0 + 8;
    float* op0 = O + t0 * (NH_ * HD_) + h * HD_;
    float* op1 = O + t1 * (NH_ * HD_) + h * HD_;
#pragma unroll
    for (int n = 0; n < 16; ++n) {
        int c = n * 8 + 2 * tg;
        float2 v0, v1;
        v0.x = oacc[n][0] * inv0; v0.y = oacc[n][1] * inv0;
        v1.x = oacc[n][2] * inv1; v1.y = oacc[n][3] * inv1;
        *(float2*)(op0 + c) = v0;
        *(float2*)(op1 + c) = v1;
    }
}

// ---------------------------------------------------------------------------
// Launch
// ---------------------------------------------------------------------------
extern "C" void kernel_launch(void* const* d_in, const int* in_sizes, int n_in,
                              void* d_out, int out_size)
{
    const float* hidden = (const float*)d_in[0];
    const int*   positions = (const int*)d_in[1];
    const float* Wq = (const float*)d_in[2];
    const float* bq = (const float*)d_in[3];
    const float* Wk = (const float*)d_in[4];
    const float* bk = (const float*)d_in[5];
    const float* Wv = (const float*)d_in[6];
    const float* bv = (const float*)d_in[7];
    const float* Wo = (const float*)d_in[8];
    float* out = (float*)d_out;

    void *pQ, *pK, *pV, *pA;
    cudaGetSymbolAddress(&pQ, g_Q);
    cudaGetSymbolAddress(&pK, g_K);
    cudaGetSymbolAddress(&pV, g_V);
    cudaGetSymbolAddress(&pA, g_ATTN);
    float* Qs = (float*)pQ;
    float* Ks = (float*)pK;
    float* Vs = (float*)pV;
    float* As = (float*)pA;

    // QKV projections (split-fp16, 2-term: full-A x Bh)
    f16_gemm_kernel<true><<<dim3((NH_ * HD_) / 128, T_ / 128), 256>>>(hidden, Wq, bq, Qs, T_, NH_ * HD_, H_);
    f16_gemm_kernel<true><<<dim3((NKV_ * HD_) / 128, T_ / 128), 256>>>(hidden, Wk, bk, Ks, T_, NKV_ * HD_, H_);
    f16_gemm_kernel<true><<<dim3((NKV_ * HD_) / 128, T_ / 128), 256>>>(hidden, Wv, bv, Vs, T_, NKV_ * HD_, H_);

    // RoPE on Q and K
    {
        int totq = T_ * NH_ * 64;
        rope_kernel<<<(totq + 255) / 256, 256>>>(Qs, positions, T_, NH_);
        int totk = T_ * NKV_ * 64;
        rope_kernel<<<(totk + 255) / 256, 256>>>(Ks, positions, T_, NKV_);
    }

    // FP16 tensor-core flash attention (BM=128, 8 warps)
    size_t fa_smem = (size_t)(FA_BM2 * QKW + 64 * QKW + FA_BM2 * VTW) * sizeof(uint32_t);
    cudaFuncSetAttribute(flash_attn_fp16_kernel, cudaFuncAttributeMaxDynamicSharedMemorySize, (int)fa_smem);
    flash_attn_fp16_kernel<<<dim3(S_ / FA_BM2, NH_, B_), 256, fa_smem>>>(Qs, Ks, Vs, As);

    // Output projection (plain fp16, 1-term)
    f16_gemm_kernel<false><<<dim3(H_ / 128, T_ / 128), 256>>>(As, Wo, nullptr, out, T_, H_, NH_ * HD_);
}